// round 1
// baseline (speedup 1.0000x reference)
#include <cuda_runtime.h>
#include <math.h>

#define B_  2
#define S_  2048
#define D_  1024
#define H_  16
#define DK_ 64
#define M_  (B_ * S_)   // 4096 rows for projection GEMMs

// Scratch (allocation-free rule: __device__ globals)
__device__ float g_Q[B_ * S_ * D_];
__device__ float g_K[B_ * S_ * D_];
__device__ float g_V[B_ * S_ * D_];
__device__ float g_O[B_ * S_ * D_];

// ---------------------------------------------------------------------------
// GEMM: out[m,n] = sum_k X[m,k] * W[n,k] + bias[n]
// M=4096, N=1024, K=1024. BM=BN=128, BK=8, 256 threads, 8x8 microtile.
// ---------------------------------------------------------------------------
__global__ __launch_bounds__(256) void gemm_bias_kernel(
    const float* __restrict__ X, const float* __restrict__ W,
    const float* __restrict__ bias, float* __restrict__ out)
{
    __shared__ float As[8][128];
    __shared__ float Ws[8][128];

    const int t  = threadIdx.x;
    const int m0 = blockIdx.y * 128;
    const int n0 = blockIdx.x * 128;

    const int lr = t >> 1;          // 0..127
    const int lc = (t & 1) * 4;     // 0 or 4

    const float* Ag = X + (size_t)(m0 + lr) * D_ + lc;
    const float* Wg = W + (size_t)(n0 + lr) * D_ + lc;

    const int ty = t >> 4;   // 0..15
    const int tx = t & 15;   // 0..15

    float acc[8][8];
#pragma unroll
    for (int i = 0; i < 8; i++)
#pragma unroll
        for (int j = 0; j < 8; j++) acc[i][j] = 0.f;

    for (int k0 = 0; k0 < D_; k0 += 8) {
        float4 av = *(const float4*)(Ag + k0);
        float4 wv = *(const float4*)(Wg + k0);
        As[lc + 0][lr] = av.x; As[lc + 1][lr] = av.y;
        As[lc + 2][lr] = av.z; As[lc + 3][lr] = av.w;
        Ws[lc + 0][lr] = wv.x; Ws[lc + 1][lr] = wv.y;
        Ws[lc + 2][lr] = wv.z; Ws[lc + 3][lr] = wv.w;
        __syncthreads();

#pragma unroll
        for (int k = 0; k < 8; k++) {
            float4 a0 = *(const float4*)&As[k][ty * 8];
            float4 a1 = *(const float4*)&As[k][ty * 8 + 4];
            float4 b0 = *(const float4*)&Ws[k][tx * 8];
            float4 b1 = *(const float4*)&Ws[k][tx * 8 + 4];
            float ar[8] = {a0.x, a0.y, a0.z, a0.w, a1.x, a1.y, a1.z, a1.w};
            float br[8] = {b0.x, b0.y, b0.z, b0.w, b1.x, b1.y, b1.z, b1.w};
#pragma unroll
            for (int i = 0; i < 8; i++)
#pragma unroll
                for (int j = 0; j < 8; j++)
                    acc[i][j] = fmaf(ar[i], br[j], acc[i][j]);
        }
        __syncthreads();
    }

    float4 bv0 = *(const float4*)&bias[n0 + tx * 8];
    float4 bv1 = *(const float4*)&bias[n0 + tx * 8 + 4];
    float bb[8] = {bv0.x, bv0.y, bv0.z, bv0.w, bv1.x, bv1.y, bv1.z, bv1.w};

#pragma unroll
    for (int i = 0; i < 8; i++) {
        int m = m0 + ty * 8 + i;
        float* op = out + (size_t)m * D_ + n0 + tx * 8;
        float4 r0 = make_float4(acc[i][0] + bb[0], acc[i][1] + bb[1],
                                acc[i][2] + bb[2], acc[i][3] + bb[3]);
        float4 r1 = make_float4(acc[i][4] + bb[4], acc[i][5] + bb[5],
                                acc[i][6] + bb[6], acc[i][7] + bb[7]);
        *(float4*)op = r0;
        *(float4*)(op + 4) = r1;
    }
}

// ---------------------------------------------------------------------------
// Causal flash attention. One block = 64 query rows of one (b,h).
// Each thread owns one q row (q + o in registers), K/V 32-key tiles in smem.
// ---------------------------------------------------------------------------
__global__ __launch_bounds__(64) void flash_kernel(
    const float* __restrict__ Q, const float* __restrict__ K,
    const float* __restrict__ V, float* __restrict__ O)
{
    __shared__ float Ks[32][64];
    __shared__ float Vs[32][64];

    const int t  = threadIdx.x;      // 0..63
    const int bh = blockIdx.y;
    const int b  = bh >> 4;
    const int h  = bh & 15;
    const int q0 = blockIdx.x * 64;
    const int qrow = q0 + t;

    const float* qp = Q + ((size_t)(b * S_ + qrow)) * D_ + h * DK_;
    float q[DK_];
#pragma unroll
    for (int i = 0; i < DK_; i += 4) {
        float4 v = *(const float4*)(qp + i);
        q[i] = v.x; q[i + 1] = v.y; q[i + 2] = v.z; q[i + 3] = v.w;
    }

    float o[DK_];
#pragma unroll
    for (int i = 0; i < DK_; i++) o[i] = 0.f;
    float mmax = -1e30f;
    float l = 0.f;

    const float* Kb = K + ((size_t)b * S_) * D_ + h * DK_;
    const float* Vb = V + ((size_t)b * S_) * D_ + h * DK_;

    const int nt = (q0 + 64 + 31) / 32;   // key tiles covering 0..q0+63

    for (int kt = 0; kt < nt; kt++) {
        const int key0 = kt * 32;

        // load 32x64 K and V tiles (coalesced float4)
#pragma unroll
        for (int j = 0; j < 8; j++) {
            int e4 = t + j * 64;
            int kk = e4 >> 4;
            int i4 = (e4 & 15) * 4;
            *(float4*)&Ks[kk][i4] = *(const float4*)(Kb + (size_t)(key0 + kk) * D_ + i4);
            *(float4*)&Vs[kk][i4] = *(const float4*)(Vb + (size_t)(key0 + kk) * D_ + i4);
        }
        __syncthreads();

        float s[32];
#pragma unroll 4
        for (int kk = 0; kk < 32; kk++) {
            float acc = 0.f;
#pragma unroll
            for (int i = 0; i < DK_; i += 4) {
                float4 kv = *(const float4*)&Ks[kk][i];
                acc = fmaf(q[i], kv.x, acc);
                acc = fmaf(q[i + 1], kv.y, acc);
                acc = fmaf(q[i + 2], kv.z, acc);
                acc = fmaf(q[i + 3], kv.w, acc);
            }
            s[kk] = acc * 0.125f;   // 1/sqrt(64)
        }

        if (key0 + 31 > q0) {       // diagonal tile: per-element causal mask
#pragma unroll
            for (int kk = 0; kk < 32; kk++)
                if (key0 + kk > qrow) s[kk] = -1e30f;
        }

        float tm = mmax;
#pragma unroll
        for (int kk = 0; kk < 32; kk++) tm = fmaxf(tm, s[kk]);

        float alpha = __expf(mmax - tm);
        mmax = tm;
        l *= alpha;
#pragma unroll
        for (int i = 0; i < DK_; i++) o[i] *= alpha;

#pragma unroll 4
        for (int kk = 0; kk < 32; kk++) {
            float p = __expf(s[kk] - tm);
            l += p;
#pragma unroll
            for (int i = 0; i < DK_; i += 4) {
                float4 vv = *(const float4*)&Vs[kk][i];
                o[i]     = fmaf(p, vv.x, o[i]);
                o[i + 1] = fmaf(p, vv.y, o[i + 1]);
                o[i + 2] = fmaf(p, vv.z, o[i + 2]);
                o[i + 3] = fmaf(p, vv.w, o[i + 3]);
            }
        }
        __syncthreads();
    }

    const float inv = 1.f / l;
    float* op = O + ((size_t)(b * S_ + qrow)) * D_ + h * DK_;
#pragma unroll
    for (int i = 0; i < DK_; i += 4) {
        float4 r = make_float4(o[i] * inv, o[i + 1] * inv,
                               o[i + 2] * inv, o[i + 3] * inv);
        *(float4*)(op + i) = r;
    }
}

// ---------------------------------------------------------------------------
extern "C" void kernel_launch(void* const* d_in, const int* in_sizes, int n_in,
                              void* d_out, int out_size)
{
    const float* query = (const float*)d_in[0];
    const float* key   = (const float*)d_in[1];
    const float* value = (const float*)d_in[2];
    const float* Wq    = (const float*)d_in[3];
    const float* bq    = (const float*)d_in[4];
    const float* Wk    = (const float*)d_in[5];
    const float* bk    = (const float*)d_in[6];
    const float* Wv    = (const float*)d_in[7];
    const float* bv    = (const float*)d_in[8];
    const float* Wo    = (const float*)d_in[9];
    const float* bo    = (const float*)d_in[10];
    float* out = (float*)d_out;

    float *pQ, *pK, *pV, *pO;
    cudaGetSymbolAddress((void**)&pQ, g_Q);
    cudaGetSymbolAddress((void**)&pK, g_K);
    cudaGetSymbolAddress((void**)&pV, g_V);
    cudaGetSymbolAddress((void**)&pO, g_O);

    dim3 gg(D_ / 128, M_ / 128);   // (8, 32)
    gemm_bias_kernel<<<gg, 256>>>(query, Wq, bq, pQ);
    gemm_bias_kernel<<<gg, 256>>>(key,   Wk, bk, pK);
    gemm_bias_kernel<<<gg, 256>>>(value, Wv, bv, pV);

    dim3 fg(S_ / 64, B_ * H_);     // (32, 32)
    flash_kernel<<<fg, 64>>>(pQ, pK, pV, pO);

    gemm_bias_kernel<<<gg, 256>>>(pO, Wo, bo, out);
}

// round 7
// speedup vs baseline: 1.6112x; 1.6112x over previous
#include <cuda_runtime.h>
#include <cuda_bf16.h>
#include <cstdint>
#include <math.h>

#define B_  2
#define S_  2048
#define D_  1024
#define H_  16
#define DK_ 64
#define M_  (B_ * S_)

// Scratch (allocation-free rule: __device__ globals)
__device__ float g_Q[M_ * D_];
__device__ float g_K[M_ * D_];
__device__ float g_V[M_ * D_];
__device__ float g_O[M_ * D_];
__device__ __nv_bfloat16 g_Ah[M_ * D_];
__device__ __nv_bfloat16 g_Al[M_ * D_];
__device__ __nv_bfloat16 g_Bh[D_ * D_];
__device__ __nv_bfloat16 g_Bl[D_ * D_];

// ---------------------------------------------------------------------------
__device__ __forceinline__ uint32_t smem_u32(const void* p) {
    return (uint32_t)__cvta_generic_to_shared(p);
}

#define CP_ASYNC16(dst_u32, src_ptr) \
    asm volatile("cp.async.cg.shared.global [%0], [%1], 16;" :: "r"(dst_u32), "l"(src_ptr))
#define CP_COMMIT() asm volatile("cp.async.commit_group;")
#define CP_WAIT(n)  asm volatile("cp.async.wait_group %0;" :: "n"(n) : "memory")

#define LDSM4(r, addr) asm volatile( \
    "ldmatrix.sync.aligned.m8n8.x4.shared.b16 {%0,%1,%2,%3}, [%4];" \
    : "=r"((r)[0]), "=r"((r)[1]), "=r"((r)[2]), "=r"((r)[3]) : "r"(addr))

#define MMA16816(d, a, b) asm volatile( \
    "mma.sync.aligned.m16n8k16.row.col.f32.bf16.bf16.f32 " \
    "{%0,%1,%2,%3}, {%4,%5,%6,%7}, {%8,%9}, {%0,%1,%2,%3};" \
    : "+f"((d)[0]), "+f"((d)[1]), "+f"((d)[2]), "+f"((d)[3]) \
    : "r"((a)[0]), "r"((a)[1]), "r"((a)[2]), "r"((a)[3]), \
      "r"((b)[0]), "r"((b)[1]))

// ---------------------------------------------------------------------------
// fp32 -> bf16 hi/lo split (elementwise, HBM-bound)
// ---------------------------------------------------------------------------
__global__ __launch_bounds__(256) void split_kernel(
    const float* __restrict__ x,
    __nv_bfloat16* __restrict__ hi, __nv_bfloat16* __restrict__ lo, int n4)
{
    int i = blockIdx.x * 256 + threadIdx.x;
    if (i >= n4) return;
    float4 v = ((const float4*)x)[i];
    __nv_bfloat16 h0 = __float2bfloat16(v.x), h1 = __float2bfloat16(v.y);
    __nv_bfloat16 h2 = __float2bfloat16(v.z), h3 = __float2bfloat16(v.w);
    __nv_bfloat16 l0 = __float2bfloat16(v.x - __bfloat162float(h0));
    __nv_bfloat16 l1 = __float2bfloat16(v.y - __bfloat162float(h1));
    __nv_bfloat16 l2 = __float2bfloat16(v.z - __bfloat162float(h2));
    __nv_bfloat16 l3 = __float2bfloat16(v.w - __bfloat162float(h3));
    ushort4 H = make_ushort4(__bfloat16_as_ushort(h0), __bfloat16_as_ushort(h1),
                             __bfloat16_as_ushort(h2), __bfloat16_as_ushort(h3));
    ushort4 L = make_ushort4(__bfloat16_as_ushort(l0), __bfloat16_as_ushort(l1),
                             __bfloat16_as_ushort(l2), __bfloat16_as_ushort(l3));
    ((ushort4*)hi)[i] = H;
    ((ushort4*)lo)[i] = L;
}

// ---------------------------------------------------------------------------
// HMMA bf16-split GEMM: out[m,n] = sum_k X[m,k]*W[n,k] + bias[n]
// Block 128x128, 8 warps (2m x 4n), warp tile 64x32, k-chunk 32, 3 stages.
// SMEM stage: Ah|Al|Bh|Bl each 128x32 bf16 (8KB), rows 64B, xor-swizzled.
// ---------------------------------------------------------------------------
#define GSTAGES 3
#define GSTAGE_BYTES 32768
#define GEMM_SMEM (GSTAGES * GSTAGE_BYTES)

__global__ __launch_bounds__(256) void gemm_mma(
    const __nv_bfloat16* __restrict__ Xh, const __nv_bfloat16* __restrict__ Xl,
    const __nv_bfloat16* __restrict__ Wh, const __nv_bfloat16* __restrict__ Wl,
    const float* __restrict__ bias, float* __restrict__ out)
{
    extern __shared__ char sb[];
    const int t = threadIdx.x, l = t & 31, wid = t >> 5;
    const int m0 = blockIdx.y * 128, n0 = blockIdx.x * 128;
    const int wm = wid >> 2, wn = wid & 3;

    // ldmatrix per-lane geometry
    const int arow = l & 15;
    const int ak8  = (l >> 4) & 1;
    const uint32_t axor = (uint32_t)((arow & 6) << 3);
    const int brow = (l & 7) + ((l >> 4) & 1) * 8;
    const int bk8  = (l >> 3) & 1;
    const uint32_t bxor = (uint32_t)((brow & 6) << 3);

    const uint32_t sbase = smem_u32(sb);

    float acc[4][4][4];
#pragma unroll
    for (int a = 0; a < 4; a++)
#pragma unroll
        for (int b = 0; b < 4; b++)
#pragma unroll
            for (int c = 0; c < 4; c++) acc[a][b][c] = 0.f;

#define GEMM_ISSUE(cc) do {                                                   \
    int _c = (cc);                                                            \
    uint32_t st = sbase + (uint32_t)((_c % GSTAGES) * GSTAGE_BYTES);          \
    int kc = _c * 32;                                                         \
    _Pragma("unroll")                                                         \
    for (int j = 0; j < 8; j++) {                                             \
        int idx = j * 256 + t;                                                \
        int half = idx >> 9;                                                  \
        int e = idx & 511;                                                    \
        int row = e >> 2;                                                     \
        uint32_t coff = (uint32_t)((e & 3) * 16);                             \
        uint32_t dst = st + (uint32_t)(half * 8192 + row * 64) +              \
                       (coff ^ ((uint32_t)(row & 6) << 3));                   \
        const __nv_bfloat16* src =                                            \
            half == 0 ? Xh + (size_t)(m0 + row) * D_ + kc + (e & 3) * 8 :     \
            half == 1 ? Xl + (size_t)(m0 + row) * D_ + kc + (e & 3) * 8 :     \
            half == 2 ? Wh + (size_t)(n0 + row) * D_ + kc + (e & 3) * 8 :     \
                        Wl + (size_t)(n0 + row) * D_ + kc + (e & 3) * 8;      \
        CP_ASYNC16(dst, src);                                                 \
    }                                                                         \
    CP_COMMIT();                                                              \
} while (0)

    GEMM_ISSUE(0);
    GEMM_ISSUE(1);

    const uint32_t aoffbase = (uint32_t)((wm * 64 + arow) * 64);
    const uint32_t boffbase = (uint32_t)((wn * 32 + brow) * 64);

    for (int c = 0; c < 32; c++) {
        CP_WAIT(1);
        __syncthreads();
        uint32_t Ah = sbase + (uint32_t)((c % GSTAGES) * GSTAGE_BYTES);
        uint32_t Al = Ah + 8192;
        uint32_t Bh = Ah + 16384;
        uint32_t Bl = Ah + 24576;

#pragma unroll
        for (int ks = 0; ks < 2; ks++) {
            uint32_t coffA = (uint32_t)(ks * 32 + ak8 * 16);
            uint32_t coffB = (uint32_t)(ks * 32 + bk8 * 16);
            uint32_t bh[8], bl[8];
#pragma unroll
            for (int nx = 0; nx < 2; nx++) {
                uint32_t off = boffbase + (uint32_t)(nx * 1024) + (coffB ^ bxor);
                LDSM4(&bh[nx * 4], Bh + off);
                LDSM4(&bl[nx * 4], Bl + off);
            }
#pragma unroll
            for (int mi = 0; mi < 4; mi++) {
                uint32_t offa = aoffbase + (uint32_t)(mi * 1024) + (coffA ^ axor);
                uint32_t ah[4], al[4];
                LDSM4(ah, Ah + offa);
                LDSM4(al, Al + offa);
#pragma unroll
                for (int ni = 0; ni < 4; ni++) {
                    MMA16816(acc[mi][ni], ah, &bh[ni * 2]);
                    MMA16816(acc[mi][ni], ah, &bl[ni * 2]);
                    MMA16816(acc[mi][ni], al, &bh[ni * 2]);
                }
            }
        }
        if (c + 2 < 32) GEMM_ISSUE(c + 2);
    }
    CP_WAIT(0);

    // epilogue: bias add + direct fp32 stores (float2 per fragment row)
#pragma unroll
    for (int mi = 0; mi < 4; mi++) {
        int r0 = m0 + wm * 64 + mi * 16 + (l >> 2);
#pragma unroll
        for (int ni = 0; ni < 4; ni++) {
            int col = n0 + wn * 32 + ni * 8 + (l & 3) * 2;
            float2 bv = *(const float2*)&bias[col];
            float2 v0 = make_float2(acc[mi][ni][0] + bv.x, acc[mi][ni][1] + bv.y);
            float2 v1 = make_float2(acc[mi][ni][2] + bv.x, acc[mi][ni][3] + bv.y);
            *(float2*)&out[(size_t)r0 * D_ + col] = v0;
            *(float2*)&out[(size_t)(r0 + 8) * D_ + col] = v1;
        }
    }
}

// ---------------------------------------------------------------------------
// Causal flash attention, 128 q-rows per block, cp.async double-buffered K/V.
// ---------------------------------------------------------------------------
__global__ __launch_bounds__(128) void flash_kernel(
    const float* __restrict__ Q, const float* __restrict__ K,
    const float* __restrict__ V, float* __restrict__ O)
{
    __shared__ float Ks[2][32][64];
    __shared__ float Vs[2][32][64];

    const int t  = threadIdx.x;      // 0..127
    const int bh = blockIdx.y;
    const int b  = bh >> 4;
    const int h  = bh & 15;
    const int q0 = blockIdx.x * 128;
    const int qrow = q0 + t;

    const float* qp = Q + ((size_t)(b * S_ + qrow)) * D_ + h * DK_;
    float q[DK_];
#pragma unroll
    for (int i = 0; i < DK_; i += 4) {
        float4 v = *(const float4*)(qp + i);
        q[i] = v.x * 0.125f; q[i + 1] = v.y * 0.125f;
        q[i + 2] = v.z * 0.125f; q[i + 3] = v.w * 0.125f;
    }

    float o[DK_];
#pragma unroll
    for (int i = 0; i < DK_; i++) o[i] = 0.f;
    float mmax = -1e30f;
    float l = 0.f;

    const float* Kb = K + ((size_t)b * S_) * D_ + h * DK_;
    const float* Vb = V + ((size_t)b * S_) * D_ + h * DK_;

    const int nt = q0 / 32 + 4;   // key tiles covering 0..q0+127

#pragma unroll
    for (int j = 0; j < 4; j++) {
        int idx = j * 128 + t;
        int row = idx >> 4;
        int c4  = (idx & 15) << 2;
        CP_ASYNC16(smem_u32(&Ks[0][row][c4]), Kb + (size_t)row * D_ + c4);
        CP_ASYNC16(smem_u32(&Vs[0][row][c4]), Vb + (size_t)row * D_ + c4);
    }
    CP_COMMIT();

    for (int kt = 0; kt < nt; kt++) {
        const int stg  = kt & 1;
        const int key0 = kt * 32;

        if (kt + 1 < nt) {
            const int nk0 = (kt + 1) * 32;
#pragma unroll
            for (int j = 0; j < 4; j++) {
                int idx = j * 128 + t;
                int row = idx >> 4;
                int c4  = (idx & 15) << 2;
                CP_ASYNC16(smem_u32(&Ks[stg ^ 1][row][c4]), Kb + (size_t)(nk0 + row) * D_ + c4);
                CP_ASYNC16(smem_u32(&Vs[stg ^ 1][row][c4]), Vb + (size_t)(nk0 + row) * D_ + c4);
            }
            CP_COMMIT();
            CP_WAIT(1);
        } else {
            CP_WAIT(0);
        }
        __syncthreads();

        if (key0 <= qrow) {
            float s[32];
#pragma unroll 4
            for (int kk = 0; kk < 32; kk++) {
                float acc = 0.f;
#pragma unroll
                for (int i = 0; i < DK_; i += 4) {
                    float4 kv = *(const float4*)&Ks[stg][kk][i];
                    acc = fmaf(q[i],     kv.x, acc);
                    acc = fmaf(q[i + 1], kv.y, acc);
                    acc = fmaf(q[i + 2], kv.z, acc);
                    acc = fmaf(q[i + 3], kv.w, acc);
                }
                s[kk] = acc;
            }

            if (key0 + 31 > qrow) {
#pragma unroll
                for (int kk = 0; kk < 32; kk++)
                    if (key0 + kk > qrow) s[kk] = -1e30f;
            }

            float tm = mmax;
#pragma unroll
            for (int kk = 0; kk < 32; kk++) tm = fmaxf(tm, s[kk]);

            float alpha = __expf(mmax - tm);
            mmax = tm;
            l *= alpha;
#pragma unroll
            for (int i = 0; i < DK_; i++) o[i] *= alpha;

#pragma unroll 4
            for (int kk = 0; kk < 32; kk++) {
                float p = __expf(s[kk] - tm);
                l += p;
#pragma unroll
                for (int i = 0; i < DK_; i += 4) {
                    float4 vv = *(const float4*)&Vs[stg][kk][i];
                    o[i]     = fmaf(p, vv.x, o[i]);
                    o[i + 1] = fmaf(p, vv.y, o[i + 1]);
                    o[i + 2] = fmaf(p, vv.z, o[i + 2]);
                    o[i + 3] = fmaf(p, vv.w, o[i + 3]);
                }
            }
        }
        __syncthreads();
    }

    const float inv = 1.f / l;
    float* op = O + ((size_t)(b * S_ + qrow)) * D_ + h * DK_;
#pragma unroll
    for (int i = 0; i < DK_; i += 4) {
        float4 r = make_float4(o[i] * inv, o[i + 1] * inv,
                               o[i + 2] * inv, o[i + 3] * inv);
        *(float4*)(op + i) = r;
    }
}

// ---------------------------------------------------------------------------
extern "C" void kernel_launch(void* const* d_in, const int* in_sizes, int n_in,
                              void* d_out, int out_size)
{
    const float* query = (const float*)d_in[0];
    const float* key   = (const float*)d_in[1];
    const float* value = (const float*)d_in[2];
    const float* Wq    = (const float*)d_in[3];
    const float* bq    = (const float*)d_in[4];
    const float* Wk    = (const float*)d_in[5];
    const float* bk    = (const float*)d_in[6];
    const float* Wv    = (const float*)d_in[7];
    const float* bv    = (const float*)d_in[8];
    const float* Wo    = (const float*)d_in[9];
    const float* bo    = (const float*)d_in[10];
    float* out = (float*)d_out;

    float *pQ, *pK, *pV, *pO;
    __nv_bfloat16 *pAh, *pAl, *pBh, *pBl;
    cudaGetSymbolAddress((void**)&pQ, g_Q);
    cudaGetSymbolAddress((void**)&pK, g_K);
    cudaGetSymbolAddress((void**)&pV, g_V);
    cudaGetSymbolAddress((void**)&pO, g_O);
    cudaGetSymbolAddress((void**)&pAh, g_Ah);
    cudaGetSymbolAddress((void**)&pAl, g_Al);
    cudaGetSymbolAddress((void**)&pBh, g_Bh);
    cudaGetSymbolAddress((void**)&pBl, g_Bl);

    cudaFuncSetAttribute(gemm_mma, cudaFuncAttributeMaxDynamicSharedMemorySize,
                         GEMM_SMEM);

    const int nA4 = M_ * D_ / 4;   // activation float4 count
    const int nW4 = D_ * D_ / 4;   // weight float4 count
    dim3 gg(D_ / 128, M_ / 128);   // (8, 32)

    split_kernel<<<nA4 / 256, 256>>>(query, pAh, pAl, nA4);
    split_kernel<<<nW4 / 256, 256>>>(Wq, pBh, pBl, nW4);
    gemm_mma<<<gg, 256, GEMM_SMEM>>>(pAh, pAl, pBh, pBl, bq, pQ);

    split_kernel<<<nA4 / 256, 256>>>(key, pAh, pAl, nA4);
    split_kernel<<<nW4 / 256, 256>>>(Wk, pBh, pBl, nW4);
    gemm_mma<<<gg, 256, GEMM_SMEM>>>(pAh, pAl, pBh, pBl, bk, pK);

    split_kernel<<<nA4 / 256, 256>>>(value, pAh, pAl, nA4);
    split_kernel<<<nW4 / 256, 256>>>(Wv, pBh, pBl, nW4);
    gemm_mma<<<gg, 256, GEMM_SMEM>>>(pAh, pAl, pBh, pBl, bv, pV);

    dim3 fg(S_ / 128, B_ * H_);    // (16, 32)
    flash_kernel<<<fg, 128>>>(pQ, pK, pV, pO);

    split_kernel<<<nA4 / 256, 256>>>(pO, pAh, pAl, nA4);
    split_kernel<<<nW4 / 256, 256>>>(Wo, pBh, pBl, nW4);
    gemm_mma<<<gg, 256, GEMM_SMEM>>>(pAh, pAl, pBh, pBl, bo, out);
}

// round 10
// speedup vs baseline: 3.3890x; 2.1033x over previous
#include <cuda_runtime.h>
#include <cuda_bf16.h>
#include <cstdint>
#include <math.h>

#define B_  2
#define S_  2048
#define D_  1024
#define H_  16
#define DK_ 64
#define M_  (B_ * S_)

// Scratch (allocation-free rule: __device__ globals)
__device__ __nv_bfloat16 g_Qh[M_ * D_];
__device__ __nv_bfloat16 g_Ql[M_ * D_];
__device__ __nv_bfloat16 g_Kh[M_ * D_];
__device__ __nv_bfloat16 g_Kl[M_ * D_];
__device__ __nv_bfloat16 g_Vh[M_ * D_];   // transposed [B,H,64,S]
__device__ __nv_bfloat16 g_Vl[M_ * D_];
__device__ __nv_bfloat16 g_Ah[M_ * D_];   // activation splits / flash O output
__device__ __nv_bfloat16 g_Al[M_ * D_];
__device__ __nv_bfloat16 g_Bh[D_ * D_];   // weight splits
__device__ __nv_bfloat16 g_Bl[D_ * D_];

// ---------------------------------------------------------------------------
__device__ __forceinline__ uint32_t smem_u32(const void* p) {
    return (uint32_t)__cvta_generic_to_shared(p);
}

#define CP_ASYNC16(dst_u32, src_ptr) \
    asm volatile("cp.async.cg.shared.global [%0], [%1], 16;" :: "r"(dst_u32), "l"(src_ptr))
#define CP_COMMIT() asm volatile("cp.async.commit_group;")
#define CP_WAIT(n)  asm volatile("cp.async.wait_group %0;" :: "n"(n) : "memory")

#define LDSM4(r, addr) asm volatile( \
    "ldmatrix.sync.aligned.m8n8.x4.shared.b16 {%0,%1,%2,%3}, [%4];" \
    : "=r"((r)[0]), "=r"((r)[1]), "=r"((r)[2]), "=r"((r)[3]) : "r"(addr))

#define MMA16816(d, a, b) asm volatile( \
    "mma.sync.aligned.m16n8k16.row.col.f32.bf16.bf16.f32 " \
    "{%0,%1,%2,%3}, {%4,%5,%6,%7}, {%8,%9}, {%0,%1,%2,%3};" \
    : "+f"((d)[0]), "+f"((d)[1]), "+f"((d)[2]), "+f"((d)[3]) \
    : "r"((a)[0]), "r"((a)[1]), "r"((a)[2]), "r"((a)[3]), \
      "r"((b)[0]), "r"((b)[1]))

__device__ __forceinline__ uint32_t pack_bf16x2(float lo, float hi) {
    uint32_t r;
    asm("cvt.rn.bf16x2.f32 %0, %1, %2;" : "=r"(r) : "f"(hi), "f"(lo));
    return r;
}

// ---------------------------------------------------------------------------
// fp32 -> bf16 hi/lo split (elementwise, HBM-bound)
// ---------------------------------------------------------------------------
__global__ __launch_bounds__(256) void split_kernel(
    const float* __restrict__ x,
    __nv_bfloat16* __restrict__ hi, __nv_bfloat16* __restrict__ lo, int n4)
{
    int i = blockIdx.x * 256 + threadIdx.x;
    if (i >= n4) return;
    float4 v = ((const float4*)x)[i];
    uint32_t h0 = pack_bf16x2(v.x, v.y);
    uint32_t h1 = pack_bf16x2(v.z, v.w);
    float r0 = v.x - __uint_as_float(h0 << 16);
    float r1 = v.y - __uint_as_float(h0 & 0xFFFF0000u);
    float r2 = v.z - __uint_as_float(h1 << 16);
    float r3 = v.w - __uint_as_float(h1 & 0xFFFF0000u);
    uint2 H = make_uint2(h0, h1);
    uint2 L = make_uint2(pack_bf16x2(r0, r1), pack_bf16x2(r2, r3));
    ((uint2*)hi)[i] = H;
    ((uint2*)lo)[i] = L;
}

// ---------------------------------------------------------------------------
// HMMA bf16-split GEMM: acc[m,n] = sum_k X[m,k]*W[n,k] (+bias, per-mode out)
// mode 0: fp32 out[m][n] = acc + bias          (final O-projection)
// mode 1: bf16 split out to [B,H,S,64], val = (acc+bias)*scale   (Q, K)
// mode 2: bf16 split out to [B,H,64,S] (transposed), val = acc+bias  (V)
// ---------------------------------------------------------------------------
#define GSTAGES 3
#define GSTAGE_BYTES 32768
#define GEMM_SMEM (GSTAGES * GSTAGE_BYTES)

__global__ __launch_bounds__(256) void gemm_mma(
    const __nv_bfloat16* __restrict__ Xh, const __nv_bfloat16* __restrict__ Xl,
    const __nv_bfloat16* __restrict__ Wh, const __nv_bfloat16* __restrict__ Wl,
    const float* __restrict__ bias, float* __restrict__ outf,
    __nv_bfloat16* __restrict__ outh, __nv_bfloat16* __restrict__ outl,
    int mode, float scale)
{
    extern __shared__ char sb[];
    const int t = threadIdx.x, l = t & 31, wid = t >> 5;
    const int m0 = blockIdx.y * 128, n0 = blockIdx.x * 128;
    const int wm = wid >> 2, wn = wid & 3;

    const int arow = l & 15;
    const int ak8  = (l >> 4) & 1;
    const uint32_t axor = (uint32_t)((arow & 6) << 3);
    const int brow = (l & 7) + ((l >> 4) & 1) * 8;
    const int bk8  = (l >> 3) & 1;
    const uint32_t bxor = (uint32_t)((brow & 6) << 3);

    const uint32_t sbase = smem_u32(sb);

    float acc[4][4][4];
#pragma unroll
    for (int a = 0; a < 4; a++)
#pragma unroll
        for (int b = 0; b < 4; b++)
#pragma unroll
            for (int c = 0; c < 4; c++) acc[a][b][c] = 0.f;

#define GEMM_ISSUE(cc) do {                                                   \
    int _c = (cc);                                                            \
    uint32_t st = sbase + (uint32_t)((_c % GSTAGES) * GSTAGE_BYTES);          \
    int kc = _c * 32;                                                         \
    _Pragma("unroll")                                                         \
    for (int j = 0; j < 8; j++) {                                             \
        int idx = j * 256 + t;                                                \
        int half = idx >> 9;                                                  \
        int e = idx & 511;                                                    \
        int row = e >> 2;                                                     \
        uint32_t coff = (uint32_t)((e & 3) * 16);                             \
        uint32_t dst = st + (uint32_t)(half * 8192 + row * 64) +              \
                       (coff ^ ((uint32_t)(row & 6) << 3));                   \
        const __nv_bfloat16* src =                                            \
            half == 0 ? Xh + (size_t)(m0 + row) * D_ + kc + (e & 3) * 8 :     \
            half == 1 ? Xl + (size_t)(m0 + row) * D_ + kc + (e & 3) * 8 :     \
            half == 2 ? Wh + (size_t)(n0 + row) * D_ + kc + (e & 3) * 8 :     \
                        Wl + (size_t)(n0 + row) * D_ + kc + (e & 3) * 8;      \
        CP_ASYNC16(dst, src);                                                 \
    }                                                                         \
    CP_COMMIT();                                                              \
} while (0)

    GEMM_ISSUE(0);
    GEMM_ISSUE(1);

    const uint32_t aoffbase = (uint32_t)((wm * 64 + arow) * 64);
    const uint32_t boffbase = (uint32_t)((wn * 32 + brow) * 64);

    for (int c = 0; c < 32; c++) {
        CP_WAIT(1);
        __syncthreads();
        uint32_t Ah = sbase + (uint32_t)((c % GSTAGES) * GSTAGE_BYTES);
        uint32_t Al = Ah + 8192;
        uint32_t Bh = Ah + 16384;
        uint32_t Bl = Ah + 24576;

#pragma unroll
        for (int ks = 0; ks < 2; ks++) {
            uint32_t coffA = (uint32_t)(ks * 32 + ak8 * 16);
            uint32_t coffB = (uint32_t)(ks * 32 + bk8 * 16);
            uint32_t bh[8], bl[8];
#pragma unroll
            for (int nx = 0; nx < 2; nx++) {
                uint32_t off = boffbase + (uint32_t)(nx * 1024) + (coffB ^ bxor);
                LDSM4(&bh[nx * 4], Bh + off);
                LDSM4(&bl[nx * 4], Bl + off);
            }
#pragma unroll
            for (int mi = 0; mi < 4; mi++) {
                uint32_t offa = aoffbase + (uint32_t)(mi * 1024) + (coffA ^ axor);
                uint32_t ah[4], al[4];
                LDSM4(ah, Ah + offa);
                LDSM4(al, Al + offa);
#pragma unroll
                for (int ni = 0; ni < 4; ni++) {
                    MMA16816(acc[mi][ni], ah, &bh[ni * 2]);
                    MMA16816(acc[mi][ni], ah, &bl[ni * 2]);
                    MMA16816(acc[mi][ni], al, &bh[ni * 2]);
                }
            }
        }
        if (c + 2 < 32) GEMM_ISSUE(c + 2);
    }
    CP_WAIT(0);

    // epilogue
#pragma unroll
    for (int mi = 0; mi < 4; mi++) {
        int r0 = m0 + wm * 64 + mi * 16 + (l >> 2);
#pragma unroll
        for (int ni = 0; ni < 4; ni++) {
            int col = n0 + wn * 32 + ni * 8 + (l & 3) * 2;
            float2 bv = *(const float2*)&bias[col];
            float v00 = acc[mi][ni][0] + bv.x, v01 = acc[mi][ni][1] + bv.y;
            float v10 = acc[mi][ni][2] + bv.x, v11 = acc[mi][ni][3] + bv.y;
            if (mode == 0) {
                *(float2*)&outf[(size_t)r0 * D_ + col] = make_float2(v00, v01);
                *(float2*)&outf[(size_t)(r0 + 8) * D_ + col] = make_float2(v10, v11);
            } else {
                v00 *= scale; v01 *= scale; v10 *= scale; v11 *= scale;
                int hh = col >> 6, d = col & 63;
#pragma unroll
                for (int rr = 0; rr < 2; rr++) {
                    int r = r0 + rr * 8;
                    float a0 = rr ? v10 : v00, a1 = rr ? v11 : v01;
                    int bb = r >> 11, s = r & 2047;
                    uint32_t ph = pack_bf16x2(a0, a1);
                    float e0 = a0 - __uint_as_float(ph << 16);
                    float e1 = a1 - __uint_as_float(ph & 0xFFFF0000u);
                    uint32_t pl = pack_bf16x2(e0, e1);
                    if (mode == 1) {
                        size_t a = ((size_t)(bb * H_ + hh) * S_ + s) * 64 + d;
                        *(uint32_t*)(outh + a) = ph;
                        *(uint32_t*)(outl + a) = pl;
                    } else {
                        size_t a = ((size_t)(bb * H_ + hh) * 64 + d) * (size_t)S_ + s;
                        outh[a]        = __ushort_as_bfloat16((unsigned short)(ph & 0xFFFF));
                        outh[a + S_]   = __ushort_as_bfloat16((unsigned short)(ph >> 16));
                        outl[a]        = __ushort_as_bfloat16((unsigned short)(pl & 0xFFFF));
                        outl[a + S_]   = __ushort_as_bfloat16((unsigned short)(pl >> 16));
                    }
                }
            }
        }
    }
}

// ---------------------------------------------------------------------------
// HMMA flash attention. CTA = 128 q rows (8 warps x 16), 64-key tiles,
// double-buffered cp.async. S = QhKh+QhKl+QlKh; PV = PhVh+PhVl+PlVh.
// Q/K in [B,H,S,64] bf16 split; V transposed [B,H,64,S] split.
// Writes O bf16 split to [M, D] (input layout of the O-projection GEMM).
// ---------------------------------------------------------------------------
#define FLASH_SMEM 98304   // 2 stages * 32KB (Kh,Kl,Vh,Vl) + 32KB Q (Qh,Ql)

__global__ __launch_bounds__(256) void flash_mma(
    const __nv_bfloat16* __restrict__ Qh, const __nv_bfloat16* __restrict__ Ql,
    const __nv_bfloat16* __restrict__ Kh, const __nv_bfloat16* __restrict__ Kl,
    const __nv_bfloat16* __restrict__ Vh, const __nv_bfloat16* __restrict__ Vl,
    __nv_bfloat16* __restrict__ Oh, __nv_bfloat16* __restrict__ Ol)
{
    extern __shared__ char sb[];
    const int t = threadIdx.x, l = t & 31, w = t >> 5;
    const int bh = blockIdx.y, b = bh >> 4, h = bh & 15;
    const int qb = (int)(gridDim.x - 1 - blockIdx.x) * 128;   // heavy CTAs first

    const uint32_t sbase = smem_u32(sb);
    const uint32_t qsm = sbase + 65536;
    const size_t base = (size_t)bh * S_ * 64;   // element base for this (b,h)

    const int arow = l & 15;
    const int ak8  = (l >> 4) & 1;
    const int brow = (l & 7) + ((l >> 4) & 1) * 8;
    const int bk8  = (l >> 3) & 1;

    // ---- load Q tile (128x64 hi+lo) to smem, group 0 ----
#pragma unroll
    for (int it = 0; it < 8; it++) {
        int idx = it * 256 + t;
        int mat = idx >> 10;            // 0 Qh, 1 Ql
        int r   = (idx >> 3) & 127;
        int c   = idx & 7;
        const __nv_bfloat16* src = (mat ? Ql : Qh) + base + (size_t)(qb + r) * 64 + c * 8;
        uint32_t dst = qsm + (uint32_t)(mat * 16384 + r * 128 + ((c ^ (r & 7)) * 16));
        CP_ASYNC16(dst, src);
    }
    CP_COMMIT();

#define FLASH_ISSUE(kt_) do {                                                 \
    int _key0 = (kt_) * 64;                                                   \
    uint32_t _st = sbase + (uint32_t)(((kt_) & 1) * 32768);                   \
    _Pragma("unroll")                                                         \
    for (int it = 0; it < 8; it++) {                                          \
        int idx = it * 256 + t;                                               \
        int mat = idx >> 9;                                                   \
        int r   = (idx >> 3) & 63;                                            \
        int c   = idx & 7;                                                    \
        const __nv_bfloat16* src;                                             \
        if      (mat == 0) src = Kh + base + (size_t)(_key0 + r) * 64 + c * 8;\
        else if (mat == 1) src = Kl + base + (size_t)(_key0 + r) * 64 + c * 8;\
        else if (mat == 2) src = Vh + base + (size_t)r * S_ + _key0 + c * 8;  \
        else               src = Vl + base + (size_t)r * S_ + _key0 + c * 8;  \
        uint32_t dst = _st + (uint32_t)(mat * 8192 + r * 128 + ((c ^ (r & 7)) * 16)); \
        CP_ASYNC16(dst, src);                                                 \
    }                                                                         \
    CP_COMMIT();                                                              \
} while (0)

    FLASH_ISSUE(0);          // group 1
    CP_WAIT(1);              // Q done
    __syncthreads();

    // ---- Q fragments to registers ----
    uint32_t qhA[4][4], qlA[4][4];
    {
        int qrow = w * 16 + arow;
        uint32_t rbase = qsm + (uint32_t)(qrow * 128);
#pragma unroll
        for (int kc = 0; kc < 4; kc++) {
            uint32_t off = (uint32_t)(((kc * 2 + ak8) ^ (qrow & 7)) * 16);
            LDSM4(qhA[kc], rbase + off);
            LDSM4(qlA[kc], rbase + 16384 + off);
        }
    }

    float O[8][4];
#pragma unroll
    for (int d = 0; d < 8; d++)
#pragma unroll
        for (int c = 0; c < 4; c++) O[d][c] = 0.f;
    float m0 = -1e30f, m1 = -1e30f, l0 = 0.f, l1 = 0.f;

    const int wmin = qb + w * 16;
    const int r0l  = wmin + (l >> 2);        // this thread's row (c0,c1)
    const int nt   = qb / 64 + 2;

    for (int kt = 0; kt < nt; kt++) {
        if (kt + 1 < nt) { FLASH_ISSUE(kt + 1); CP_WAIT(1); }
        else             { CP_WAIT(0); }
        __syncthreads();

        const int key0 = kt * 64;
        if (key0 <= wmin + 15) {
            uint32_t st = sbase + (uint32_t)((kt & 1) * 32768);

            // ---- S = Q K^T (3-term split) ----
            float S[8][4];
#pragma unroll
            for (int nf = 0; nf < 8; nf++)
#pragma unroll
                for (int c = 0; c < 4; c++) S[nf][c] = 0.f;

#pragma unroll
            for (int kc = 0; kc < 4; kc++) {
                uint32_t kbh[16], kbl[16];
#pragma unroll
                for (int g = 0; g < 4; g++) {
                    int row = g * 16 + brow;
                    uint32_t off = (uint32_t)(row * 128 + (((kc * 2 + bk8) ^ (row & 7)) * 16));
                    LDSM4(&kbh[g * 4], st + off);
                    LDSM4(&kbl[g * 4], st + 8192 + off);
                }
#pragma unroll
                for (int nf = 0; nf < 8; nf++) {
                    int ix = (nf >> 1) * 4 + (nf & 1) * 2;
                    MMA16816(S[nf], qhA[kc], &kbh[ix]);
                    MMA16816(S[nf], qhA[kc], &kbl[ix]);
                    MMA16816(S[nf], qlA[kc], &kbh[ix]);
                }
            }

            // ---- causal mask (diagonal tiles only) ----
            if (key0 + 63 > wmin) {
#pragma unroll
                for (int nf = 0; nf < 8; nf++) {
                    int k0 = key0 + nf * 8 + (l & 3) * 2;
                    if (k0     > r0l)     S[nf][0] = -1e30f;
                    if (k0 + 1 > r0l)     S[nf][1] = -1e30f;
                    if (k0     > r0l + 8) S[nf][2] = -1e30f;
                    if (k0 + 1 > r0l + 8) S[nf][3] = -1e30f;
                }
            }

            // ---- online softmax ----
            float mx0 = -1e30f, mx1 = -1e30f;
#pragma unroll
            for (int nf = 0; nf < 8; nf++) {
                mx0 = fmaxf(mx0, fmaxf(S[nf][0], S[nf][1]));
                mx1 = fmaxf(mx1, fmaxf(S[nf][2], S[nf][3]));
            }
            mx0 = fmaxf(mx0, __shfl_xor_sync(0xFFFFFFFF, mx0, 1));
            mx0 = fmaxf(mx0, __shfl_xor_sync(0xFFFFFFFF, mx0, 2));
            mx1 = fmaxf(mx1, __shfl_xor_sync(0xFFFFFFFF, mx1, 1));
            mx1 = fmaxf(mx1, __shfl_xor_sync(0xFFFFFFFF, mx1, 2));

            float mn0 = fmaxf(m0, mx0), mn1 = fmaxf(m1, mx1);
            float al0 = __expf(m0 - mn0), al1 = __expf(m1 - mn1);
            m0 = mn0; m1 = mn1;

            uint32_t pha[4][4], pla[4][4];
            float rs0 = 0.f, rs1 = 0.f;
#pragma unroll
            for (int nf = 0; nf < 8; nf++) {
                float p00 = __expf(S[nf][0] - mn0);
                float p01 = __expf(S[nf][1] - mn0);
                float p10 = __expf(S[nf][2] - mn1);
                float p11 = __expf(S[nf][3] - mn1);
                rs0 += p00 + p01; rs1 += p10 + p11;
                int kc = nf >> 1, a0 = (nf & 1) * 2;
                uint32_t u0 = pack_bf16x2(p00, p01);
                uint32_t u1 = pack_bf16x2(p10, p11);
                pha[kc][a0]     = u0;
                pha[kc][a0 + 1] = u1;
                float e00 = p00 - __uint_as_float(u0 << 16);
                float e01 = p01 - __uint_as_float(u0 & 0xFFFF0000u);
                float e10 = p10 - __uint_as_float(u1 << 16);
                float e11 = p11 - __uint_as_float(u1 & 0xFFFF0000u);
                pla[kc][a0]     = pack_bf16x2(e00, e01);
                pla[kc][a0 + 1] = pack_bf16x2(e10, e11);
            }
            rs0 += __shfl_xor_sync(0xFFFFFFFF, rs0, 1);
            rs0 += __shfl_xor_sync(0xFFFFFFFF, rs0, 2);
            rs1 += __shfl_xor_sync(0xFFFFFFFF, rs1, 1);
            rs1 += __shfl_xor_sync(0xFFFFFFFF, rs1, 2);
            l0 = l0 * al0 + rs0;
            l1 = l1 * al1 + rs1;

#pragma unroll
            for (int d = 0; d < 8; d++) {
                O[d][0] *= al0; O[d][1] *= al0;
                O[d][2] *= al1; O[d][3] *= al1;
            }

            // ---- O += P V (3-term split) ----
#pragma unroll
            for (int kc = 0; kc < 4; kc++) {
                uint32_t vbh[16], vbl[16];
#pragma unroll
                for (int g = 0; g < 4; g++) {
                    int row = g * 16 + brow;
                    uint32_t off = (uint32_t)(row * 128 + (((kc * 2 + bk8) ^ (row & 7)) * 16));
                    LDSM4(&vbh[g * 4], st + 16384 + off);
                    LDSM4(&vbl[g * 4], st + 24576 + off);
                }
#pragma unroll
                for (int df = 0; df < 8; df++) {
                    int ix = (df >> 1) * 4 + (df & 1) * 2;
                    MMA16816(O[df], pha[kc], &vbh[ix]);
                    MMA16816(O[df], pha[kc], &vbl[ix]);
                    MMA16816(O[df], pla[kc], &vbh[ix]);
                }
            }
        }
        __syncthreads();
    }

    // ---- write O bf16 split to [M, D] layout ----
    const float inv0 = 1.f / l0, inv1 = 1.f / l1;
    const int r0g = qb + w * 16 + (l >> 2);
#pragma unroll
    for (int df = 0; df < 8; df++) {
        int d = df * 8 + (l & 3) * 2;
        float v0 = O[df][0] * inv0, v1 = O[df][1] * inv0;
        float v2 = O[df][2] * inv1, v3 = O[df][3] * inv1;
        size_t a0 = ((size_t)(b * S_ + r0g)) * D_ + h * 64 + d;
        size_t a1 = ((size_t)(b * S_ + r0g + 8)) * D_ + h * 64 + d;
        uint32_t u0 = pack_bf16x2(v0, v1);
        uint32_t u1 = pack_bf16x2(v2, v3);
        float e00 = v0 - __uint_as_float(u0 << 16);
        float e01 = v1 - __uint_as_float(u0 & 0xFFFF0000u);
        float e10 = v2 - __uint_as_float(u1 << 16);
        float e11 = v3 - __uint_as_float(u1 & 0xFFFF0000u);
        *(uint32_t*)(Oh + a0) = u0;
        *(uint32_t*)(Oh + a1) = u1;
        *(uint32_t*)(Ol + a0) = pack_bf16x2(e00, e01);
        *(uint32_t*)(Ol + a1) = pack_bf16x2(e10, e11);
    }
}

// ---------------------------------------------------------------------------
extern "C" void kernel_launch(void* const* d_in, const int* in_sizes, int n_in,
                              void* d_out, int out_size)
{
    const float* query = (const float*)d_in[0];
    const float* key   = (const float*)d_in[1];
    const float* value = (const float*)d_in[2];
    const float* Wq    = (const float*)d_in[3];
    const float* bq    = (const float*)d_in[4];
    const float* Wk    = (const float*)d_in[5];
    const float* bk    = (const float*)d_in[6];
    const float* Wv    = (const float*)d_in[7];
    const float* bv    = (const float*)d_in[8];
    const float* Wo    = (const float*)d_in[9];
    const float* bo    = (const float*)d_in[10];
    float* out = (float*)d_out;

    __nv_bfloat16 *pQh, *pQl, *pKh, *pKl, *pVh, *pVl, *pAh, *pAl, *pBh, *pBl;
    cudaGetSymbolAddress((void**)&pQh, g_Qh);
    cudaGetSymbolAddress((void**)&pQl, g_Ql);
    cudaGetSymbolAddress((void**)&pKh, g_Kh);
    cudaGetSymbolAddress((void**)&pKl, g_Kl);
    cudaGetSymbolAddress((void**)&pVh, g_Vh);
    cudaGetSymbolAddress((void**)&pVl, g_Vl);
    cudaGetSymbolAddress((void**)&pAh, g_Ah);
    cudaGetSymbolAddress((void**)&pAl, g_Al);
    cudaGetSymbolAddress((void**)&pBh, g_Bh);
    cudaGetSymbolAddress((void**)&pBl, g_Bl);

    cudaFuncSetAttribute(gemm_mma, cudaFuncAttributeMaxDynamicSharedMemorySize,
                         GEMM_SMEM);
    cudaFuncSetAttribute(flash_mma, cudaFuncAttributeMaxDynamicSharedMemorySize,
                         FLASH_SMEM);

    const int nA4 = M_ * D_ / 4;
    const int nW4 = D_ * D_ / 4;
    dim3 gg(D_ / 128, M_ / 128);   // (8, 32)

    // Q projection (scale 1/8 folded in)
    split_kernel<<<nA4 / 256, 256>>>(query, pAh, pAl, nA4);
    split_kernel<<<nW4 / 256, 256>>>(Wq, pBh, pBl, nW4);
    gemm_mma<<<gg, 256, GEMM_SMEM>>>(pAh, pAl, pBh, pBl, bq, nullptr, pQh, pQl, 1, 0.125f);

    // K projection
    split_kernel<<<nA4 / 256, 256>>>(key, pAh, pAl, nA4);
    split_kernel<<<nW4 / 256, 256>>>(Wk, pBh, pBl, nW4);
    gemm_mma<<<gg, 256, GEMM_SMEM>>>(pAh, pAl, pBh, pBl, bk, nullptr, pKh, pKl, 1, 1.0f);

    // V projection (transposed split output)
    split_kernel<<<nA4 / 256, 256>>>(value, pAh, pAl, nA4);
    split_kernel<<<nW4 / 256, 256>>>(Wv, pBh, pBl, nW4);
    gemm_mma<<<gg, 256, GEMM_SMEM>>>(pAh, pAl, pBh, pBl, bv, nullptr, pVh, pVl, 2, 1.0f);

    // attention (writes split O into pAh/pAl)
    dim3 fg(S_ / 128, B_ * H_);    // (16, 32)
    flash_mma<<<fg, 256, FLASH_SMEM>>>(pQh, pQl, pKh, pKl, pVh, pVl, pAh, pAl);

    // O projection -> fp32 out
    split_kernel<<<nW4 / 256, 256>>>(Wo, pBh, pBl, nW4);
    gemm_mma<<<gg, 256, GEMM_SMEM>>>(pAh, pAl, pBh, pBl, bo, out, nullptr, nullptr, 0, 1.0f);
}

// round 11
// speedup vs baseline: 3.7205x; 1.0978x over previous
#include <cuda_runtime.h>
#include <cuda_bf16.h>
#include <cstdint>
#include <math.h>

#define B_  2
#define S_  2048
#define D_  1024
#define H_  16
#define DK_ 64
#define M_  (B_ * S_)

// Scratch (allocation-free rule: __device__ globals)
__device__ __nv_bfloat16 g_Qh[M_ * D_];
__device__ __nv_bfloat16 g_Ql[M_ * D_];
__device__ __nv_bfloat16 g_Kh[M_ * D_];
__device__ __nv_bfloat16 g_Kl[M_ * D_];
__device__ __nv_bfloat16 g_Vh[M_ * D_];   // transposed [B,H,64,S]
__device__ __nv_bfloat16 g_Vl[M_ * D_];
// activation splits (query/key/value); aQ reused as flash O output
__device__ __nv_bfloat16 g_aQh[M_ * D_];
__device__ __nv_bfloat16 g_aQl[M_ * D_];
__device__ __nv_bfloat16 g_aKh[M_ * D_];
__device__ __nv_bfloat16 g_aKl[M_ * D_];
__device__ __nv_bfloat16 g_aVh[M_ * D_];
__device__ __nv_bfloat16 g_aVl[M_ * D_];
// weight splits
__device__ __nv_bfloat16 g_wQh[D_ * D_];
__device__ __nv_bfloat16 g_wQl[D_ * D_];
__device__ __nv_bfloat16 g_wKh[D_ * D_];
__device__ __nv_bfloat16 g_wKl[D_ * D_];
__device__ __nv_bfloat16 g_wVh[D_ * D_];
__device__ __nv_bfloat16 g_wVl[D_ * D_];
__device__ __nv_bfloat16 g_wOh[D_ * D_];
__device__ __nv_bfloat16 g_wOl[D_ * D_];

// ---------------------------------------------------------------------------
__device__ __forceinline__ uint32_t smem_u32(const void* p) {
    return (uint32_t)__cvta_generic_to_shared(p);
}

#define CP_ASYNC16(dst_u32, src_ptr) \
    asm volatile("cp.async.cg.shared.global [%0], [%1], 16;" :: "r"(dst_u32), "l"(src_ptr))
#define CP_COMMIT() asm volatile("cp.async.commit_group;")
#define CP_WAIT(n)  asm volatile("cp.async.wait_group %0;" :: "n"(n) : "memory")

#define LDSM4(r, addr) asm volatile( \
    "ldmatrix.sync.aligned.m8n8.x4.shared.b16 {%0,%1,%2,%3}, [%4];" \
    : "=r"((r)[0]), "=r"((r)[1]), "=r"((r)[2]), "=r"((r)[3]) : "r"(addr))

#define MMA16816(d, a, b) asm volatile( \
    "mma.sync.aligned.m16n8k16.row.col.f32.bf16.bf16.f32 " \
    "{%0,%1,%2,%3}, {%4,%5,%6,%7}, {%8,%9}, {%0,%1,%2,%3};" \
    : "+f"((d)[0]), "+f"((d)[1]), "+f"((d)[2]), "+f"((d)[3]) \
    : "r"((a)[0]), "r"((a)[1]), "r"((a)[2]), "r"((a)[3]), \
      "r"((b)[0]), "r"((b)[1]))

__device__ __forceinline__ uint32_t pack_bf16x2(float lo, float hi) {
    uint32_t r;
    asm("cvt.rn.bf16x2.f32 %0, %1, %2;" : "=r"(r) : "f"(hi), "f"(lo));
    return r;
}

// ---------------------------------------------------------------------------
// fused fp32 -> bf16 hi/lo split for all 7 tensors, 4 float4 per thread
// ---------------------------------------------------------------------------
struct SJobs {
    const float* src[7];
    __nv_bfloat16* hi[7];
    __nv_bfloat16* lo[7];
    int n4[7];
};

__global__ __launch_bounds__(256) void split_all(SJobs s)
{
    const int z = blockIdx.y;
    const int n4 = s.n4[z];
    const float* __restrict__ x = s.src[z];
    __nv_bfloat16* __restrict__ hi = s.hi[z];
    __nv_bfloat16* __restrict__ lo = s.lo[z];

    int i0 = blockIdx.x * 1024 + threadIdx.x;
    if (i0 >= n4) return;
#pragma unroll
    for (int j = 0; j < 4; j++) {
        int i = i0 + j * 256;
        if (i < n4) {
            float4 v = ((const float4*)x)[i];
            uint32_t h0 = pack_bf16x2(v.x, v.y);
            uint32_t h1 = pack_bf16x2(v.z, v.w);
            float r0 = v.x - __uint_as_float(h0 << 16);
            float r1 = v.y - __uint_as_float(h0 & 0xFFFF0000u);
            float r2 = v.z - __uint_as_float(h1 << 16);
            float r3 = v.w - __uint_as_float(h1 & 0xFFFF0000u);
            ((uint2*)hi)[i] = make_uint2(h0, h1);
            ((uint2*)lo)[i] = make_uint2(pack_bf16x2(r0, r1), pack_bf16x2(r2, r3));
        }
    }
}

// ---------------------------------------------------------------------------
// HMMA bf16-split GEMM, multi-job (grid.z selects job).
// mode 0: fp32 out = acc + bias
// mode 1: bf16 split out to [B,H,S,64], val = (acc+bias)*scale
// mode 2: bf16 split out to [B,H,64,S] (transposed), val = acc+bias
// ---------------------------------------------------------------------------
#define GSTAGES 3
#define GSTAGE_BYTES 32768
#define GEMM_SMEM (GSTAGES * GSTAGE_BYTES)

struct GJob {
    const __nv_bfloat16 *Xh, *Xl, *Wh, *Wl;
    const float* bias;
    float* outf;
    __nv_bfloat16 *oh, *ol;
    int mode;
    float scale;
};
struct GJobs { GJob j[3]; };

__global__ __launch_bounds__(256) void gemm_mma(GJobs jobs)
{
    extern __shared__ char sb[];
    const GJob jb = jobs.j[blockIdx.z];
    const __nv_bfloat16* __restrict__ Xh = jb.Xh;
    const __nv_bfloat16* __restrict__ Xl = jb.Xl;
    const __nv_bfloat16* __restrict__ Wh = jb.Wh;
    const __nv_bfloat16* __restrict__ Wl = jb.Wl;

    const int t = threadIdx.x, l = t & 31, wid = t >> 5;
    const int m0 = blockIdx.y * 128, n0 = blockIdx.x * 128;
    const int wm = wid >> 2, wn = wid & 3;

    const int arow = l & 15;
    const int ak8  = (l >> 4) & 1;
    const uint32_t axor = (uint32_t)((arow & 6) << 3);
    const int brow = (l & 7) + ((l >> 4) & 1) * 8;
    const int bk8  = (l >> 3) & 1;
    const uint32_t bxor = (uint32_t)((brow & 6) << 3);

    const uint32_t sbase = smem_u32(sb);

    float acc[4][4][4];
#pragma unroll
    for (int a = 0; a < 4; a++)
#pragma unroll
        for (int b = 0; b < 4; b++)
#pragma unroll
            for (int c = 0; c < 4; c++) acc[a][b][c] = 0.f;

#define GEMM_ISSUE(cc) do {                                                   \
    int _c = (cc);                                                            \
    uint32_t st = sbase + (uint32_t)((_c % GSTAGES) * GSTAGE_BYTES);          \
    int kc = _c * 32;                                                         \
    _Pragma("unroll")                                                         \
    for (int j = 0; j < 8; j++) {                                             \
        int idx = j * 256 + t;                                                \
        int half = idx >> 9;                                                  \
        int e = idx & 511;                                                    \
        int row = e >> 2;                                                     \
        uint32_t coff = (uint32_t)((e & 3) * 16);                             \
        uint32_t dst = st + (uint32_t)(half * 8192 + row * 64) +              \
                       (coff ^ ((uint32_t)(row & 6) << 3));                   \
        const __nv_bfloat16* src =                                            \
            half == 0 ? Xh + (size_t)(m0 + row) * D_ + kc + (e & 3) * 8 :     \
            half == 1 ? Xl + (size_t)(m0 + row) * D_ + kc + (e & 3) * 8 :     \
            half == 2 ? Wh + (size_t)(n0 + row) * D_ + kc + (e & 3) * 8 :     \
                        Wl + (size_t)(n0 + row) * D_ + kc + (e & 3) * 8;      \
        CP_ASYNC16(dst, src);                                                 \
    }                                                                         \
    CP_COMMIT();                                                              \
} while (0)

    GEMM_ISSUE(0);
    GEMM_ISSUE(1);

    const uint32_t aoffbase = (uint32_t)((wm * 64 + arow) * 64);
    const uint32_t boffbase = (uint32_t)((wn * 32 + brow) * 64);

    for (int c = 0; c < 32; c++) {
        CP_WAIT(1);
        __syncthreads();
        uint32_t Ah = sbase + (uint32_t)((c % GSTAGES) * GSTAGE_BYTES);
        uint32_t Al = Ah + 8192;
        uint32_t Bh = Ah + 16384;
        uint32_t Bl = Ah + 24576;

#pragma unroll
        for (int ks = 0; ks < 2; ks++) {
            uint32_t coffA = (uint32_t)(ks * 32 + ak8 * 16);
            uint32_t coffB = (uint32_t)(ks * 32 + bk8 * 16);
            uint32_t bh[8], bl[8];
#pragma unroll
            for (int nx = 0; nx < 2; nx++) {
                uint32_t off = boffbase + (uint32_t)(nx * 1024) + (coffB ^ bxor);
                LDSM4(&bh[nx * 4], Bh + off);
                LDSM4(&bl[nx * 4], Bl + off);
            }
#pragma unroll
            for (int mi = 0; mi < 4; mi++) {
                uint32_t offa = aoffbase + (uint32_t)(mi * 1024) + (coffA ^ axor);
                uint32_t ah[4], al[4];
                LDSM4(ah, Ah + offa);
                LDSM4(al, Al + offa);
#pragma unroll
                for (int ni = 0; ni < 4; ni++) {
                    MMA16816(acc[mi][ni], ah, &bh[ni * 2]);
                    MMA16816(acc[mi][ni], ah, &bl[ni * 2]);
                    MMA16816(acc[mi][ni], al, &bh[ni * 2]);
                }
            }
        }
        if (c + 2 < 32) GEMM_ISSUE(c + 2);
    }
    CP_WAIT(0);

    // epilogue
    const int mode = jb.mode;
    const float scale = jb.scale;
#pragma unroll
    for (int mi = 0; mi < 4; mi++) {
        int r0 = m0 + wm * 64 + mi * 16 + (l >> 2);
#pragma unroll
        for (int ni = 0; ni < 4; ni++) {
            int col = n0 + wn * 32 + ni * 8 + (l & 3) * 2;
            float2 bv = *(const float2*)&jb.bias[col];
            float v00 = acc[mi][ni][0] + bv.x, v01 = acc[mi][ni][1] + bv.y;
            float v10 = acc[mi][ni][2] + bv.x, v11 = acc[mi][ni][3] + bv.y;
            if (mode == 0) {
                *(float2*)&jb.outf[(size_t)r0 * D_ + col] = make_float2(v00, v01);
                *(float2*)&jb.outf[(size_t)(r0 + 8) * D_ + col] = make_float2(v10, v11);
            } else {
                v00 *= scale; v01 *= scale; v10 *= scale; v11 *= scale;
                int hh = col >> 6, d = col & 63;
#pragma unroll
                for (int rr = 0; rr < 2; rr++) {
                    int r = r0 + rr * 8;
                    float a0 = rr ? v10 : v00, a1 = rr ? v11 : v01;
                    int bb = r >> 11, s = r & 2047;
                    uint32_t ph = pack_bf16x2(a0, a1);
                    float e0 = a0 - __uint_as_float(ph << 16);
                    float e1 = a1 - __uint_as_float(ph & 0xFFFF0000u);
                    uint32_t pl = pack_bf16x2(e0, e1);
                    if (mode == 1) {
                        size_t a = ((size_t)(bb * H_ + hh) * S_ + s) * 64 + d;
                        *(uint32_t*)(jb.oh + a) = ph;
                        *(uint32_t*)(jb.ol + a) = pl;
                    } else {
                        size_t a = ((size_t)(bb * H_ + hh) * 64 + d) * (size_t)S_ + s;
                        jb.oh[a]      = __ushort_as_bfloat16((unsigned short)(ph & 0xFFFF));
                        jb.oh[a + S_] = __ushort_as_bfloat16((unsigned short)(ph >> 16));
                        jb.ol[a]      = __ushort_as_bfloat16((unsigned short)(pl & 0xFFFF));
                        jb.ol[a + S_] = __ushort_as_bfloat16((unsigned short)(pl >> 16));
                    }
                }
            }
        }
    }
}

// ---------------------------------------------------------------------------
// HMMA flash attention (unchanged from R10-verified version).
// ---------------------------------------------------------------------------
#define FLASH_SMEM 98304

__global__ __launch_bounds__(256) void flash_mma(
    const __nv_bfloat16* __restrict__ Qh, const __nv_bfloat16* __restrict__ Ql,
    const __nv_bfloat16* __restrict__ Kh, const __nv_bfloat16* __restrict__ Kl,
    const __nv_bfloat16* __restrict__ Vh, const __nv_bfloat16* __restrict__ Vl,
    __nv_bfloat16* __restrict__ Oh, __nv_bfloat16* __restrict__ Ol)
{
    extern __shared__ char sb[];
    const int t = threadIdx.x, l = t & 31, w = t >> 5;
    const int bh = blockIdx.y, b = bh >> 4, h = bh & 15;
    const int qb = (int)(gridDim.x - 1 - blockIdx.x) * 128;

    const uint32_t sbase = smem_u32(sb);
    const uint32_t qsm = sbase + 65536;
    const size_t base = (size_t)bh * S_ * 64;

    const int arow = l & 15;
    const int ak8  = (l >> 4) & 1;
    const int brow = (l & 7) + ((l >> 4) & 1) * 8;
    const int bk8  = (l >> 3) & 1;

#pragma unroll
    for (int it = 0; it < 8; it++) {
        int idx = it * 256 + t;
        int mat = idx >> 10;
        int r   = (idx >> 3) & 127;
        int c   = idx & 7;
        const __nv_bfloat16* src = (mat ? Ql : Qh) + base + (size_t)(qb + r) * 64 + c * 8;
        uint32_t dst = qsm + (uint32_t)(mat * 16384 + r * 128 + ((c ^ (r & 7)) * 16));
        CP_ASYNC16(dst, src);
    }
    CP_COMMIT();

#define FLASH_ISSUE(kt_) do {                                                 \
    int _key0 = (kt_) * 64;                                                   \
    uint32_t _st = sbase + (uint32_t)(((kt_) & 1) * 32768);                   \
    _Pragma("unroll")                                                         \
    for (int it = 0; it < 8; it++) {                                          \
        int idx = it * 256 + t;                                               \
        int mat = idx >> 9;                                                   \
        int r   = (idx >> 3) & 63;                                            \
        int c   = idx & 7;                                                    \
        const __nv_bfloat16* src;                                             \
        if      (mat == 0) src = Kh + base + (size_t)(_key0 + r) * 64 + c * 8;\
        else if (mat == 1) src = Kl + base + (size_t)(_key0 + r) * 64 + c * 8;\
        else if (mat == 2) src = Vh + base + (size_t)r * S_ + _key0 + c * 8;  \
        else               src = Vl + base + (size_t)r * S_ + _key0 + c * 8;  \
        uint32_t dst = _st + (uint32_t)(mat * 8192 + r * 128 + ((c ^ (r & 7)) * 16)); \
        CP_ASYNC16(dst, src);                                                 \
    }                                                                         \
    CP_COMMIT();                                                              \
} while (0)

    FLASH_ISSUE(0);
    CP_WAIT(1);
    __syncthreads();

    uint32_t qhA[4][4], qlA[4][4];
    {
        int qrow = w * 16 + arow;
        uint32_t rbase = qsm + (uint32_t)(qrow * 128);
#pragma unroll
        for (int kc = 0; kc < 4; kc++) {
            uint32_t off = (uint32_t)(((kc * 2 + ak8) ^ (qrow & 7)) * 16);
            LDSM4(qhA[kc], rbase + off);
            LDSM4(qlA[kc], rbase + 16384 + off);
        }
    }

    float O[8][4];
#pragma unroll
    for (int d = 0; d < 8; d++)
#pragma unroll
        for (int c = 0; c < 4; c++) O[d][c] = 0.f;
    float m0 = -1e30f, m1 = -1e30f, l0 = 0.f, l1 = 0.f;

    const int wmin = qb + w * 16;
    const int r0l  = wmin + (l >> 2);
    const int nt   = qb / 64 + 2;

    for (int kt = 0; kt < nt; kt++) {
        if (kt + 1 < nt) { FLASH_ISSUE(kt + 1); CP_WAIT(1); }
        else             { CP_WAIT(0); }
        __syncthreads();

        const int key0 = kt * 64;
        if (key0 <= wmin + 15) {
            uint32_t st = sbase + (uint32_t)((kt & 1) * 32768);

            float S[8][4];
#pragma unroll
            for (int nf = 0; nf < 8; nf++)
#pragma unroll
                for (int c = 0; c < 4; c++) S[nf][c] = 0.f;

#pragma unroll
            for (int kc = 0; kc < 4; kc++) {
                uint32_t kbh[16], kbl[16];
#pragma unroll
                for (int g = 0; g < 4; g++) {
                    int row = g * 16 + brow;
                    uint32_t off = (uint32_t)(row * 128 + (((kc * 2 + bk8) ^ (row & 7)) * 16));
                    LDSM4(&kbh[g * 4], st + off);
                    LDSM4(&kbl[g * 4], st + 8192 + off);
                }
#pragma unroll
                for (int nf = 0; nf < 8; nf++) {
                    int ix = (nf >> 1) * 4 + (nf & 1) * 2;
                    MMA16816(S[nf], qhA[kc], &kbh[ix]);
                    MMA16816(S[nf], qhA[kc], &kbl[ix]);
                    MMA16816(S[nf], qlA[kc], &kbh[ix]);
                }
            }

            if (key0 + 63 > wmin) {
#pragma unroll
                for (int nf = 0; nf < 8; nf++) {
                    int k0 = key0 + nf * 8 + (l & 3) * 2;
                    if (k0     > r0l)     S[nf][0] = -1e30f;
                    if (k0 + 1 > r0l)     S[nf][1] = -1e30f;
                    if (k0     > r0l + 8) S[nf][2] = -1e30f;
                    if (k0 + 1 > r0l + 8) S[nf][3] = -1e30f;
                }
            }

            float mx0 = -1e30f, mx1 = -1e30f;
#pragma unroll
            for (int nf = 0; nf < 8; nf++) {
                mx0 = fmaxf(mx0, fmaxf(S[nf][0], S[nf][1]));
                mx1 = fmaxf(mx1, fmaxf(S[nf][2], S[nf][3]));
            }
            mx0 = fmaxf(mx0, __shfl_xor_sync(0xFFFFFFFF, mx0, 1));
            mx0 = fmaxf(mx0, __shfl_xor_sync(0xFFFFFFFF, mx0, 2));
            mx1 = fmaxf(mx1, __shfl_xor_sync(0xFFFFFFFF, mx1, 1));
            mx1 = fmaxf(mx1, __shfl_xor_sync(0xFFFFFFFF, mx1, 2));

            float mn0 = fmaxf(m0, mx0), mn1 = fmaxf(m1, mx1);
            float al0 = __expf(m0 - mn0), al1 = __expf(m1 - mn1);
            m0 = mn0; m1 = mn1;

            uint32_t pha[4][4], pla[4][4];
            float rs0 = 0.f, rs1 = 0.f;
#pragma unroll
            for (int nf = 0; nf < 8; nf++) {
                float p00 = __expf(S[nf][0] - mn0);
                float p01 = __expf(S[nf][1] - mn0);
                float p10 = __expf(S[nf][2] - mn1);
                float p11 = __expf(S[nf][3] - mn1);
                rs0 += p00 + p01; rs1 += p10 + p11;
                int kc = nf >> 1, a0 = (nf & 1) * 2;
                uint32_t u0 = pack_bf16x2(p00, p01);
                uint32_t u1 = pack_bf16x2(p10, p11);
                pha[kc][a0]     = u0;
                pha[kc][a0 + 1] = u1;
                float e00 = p00 - __uint_as_float(u0 << 16);
                float e01 = p01 - __uint_as_float(u0 & 0xFFFF0000u);
                float e10 = p10 - __uint_as_float(u1 << 16);
                float e11 = p11 - __uint_as_float(u1 & 0xFFFF0000u);
                pla[kc][a0]     = pack_bf16x2(e00, e01);
                pla[kc][a0 + 1] = pack_bf16x2(e10, e11);
            }
            rs0 += __shfl_xor_sync(0xFFFFFFFF, rs0, 1);
            rs0 += __shfl_xor_sync(0xFFFFFFFF, rs0, 2);
            rs1 += __shfl_xor_sync(0xFFFFFFFF, rs1, 1);
            rs1 += __shfl_xor_sync(0xFFFFFFFF, rs1, 2);
            l0 = l0 * al0 + rs0;
            l1 = l1 * al1 + rs1;

#pragma unroll
            for (int d = 0; d < 8; d++) {
                O[d][0] *= al0; O[d][1] *= al0;
                O[d][2] *= al1; O[d][3] *= al1;
            }

#pragma unroll
            for (int kc = 0; kc < 4; kc++) {
                uint32_t vbh[16], vbl[16];
#pragma unroll
                for (int g = 0; g < 4; g++) {
                    int row = g * 16 + brow;
                    uint32_t off = (uint32_t)(row * 128 + (((kc * 2 + bk8) ^ (row & 7)) * 16));
                    LDSM4(&vbh[g * 4], st + 16384 + off);
                    LDSM4(&vbl[g * 4], st + 24576 + off);
                }
#pragma unroll
                for (int df = 0; df < 8; df++) {
                    int ix = (df >> 1) * 4 + (df & 1) * 2;
                    MMA16816(O[df], pha[kc], &vbh[ix]);
                    MMA16816(O[df], pha[kc], &vbl[ix]);
                    MMA16816(O[df], pla[kc], &vbh[ix]);
                }
            }
        }
        __syncthreads();
    }

    const float inv0 = 1.f / l0, inv1 = 1.f / l1;
    const int r0g = qb + w * 16 + (l >> 2);
#pragma unroll
    for (int df = 0; df < 8; df++) {
        int d = df * 8 + (l & 3) * 2;
        float v0 = O[df][0] * inv0, v1 = O[df][1] * inv0;
        float v2 = O[df][2] * inv1, v3 = O[df][3] * inv1;
        size_t a0 = ((size_t)(b * S_ + r0g)) * D_ + h * 64 + d;
        size_t a1 = ((size_t)(b * S_ + r0g + 8)) * D_ + h * 64 + d;
        uint32_t u0 = pack_bf16x2(v0, v1);
        uint32_t u1 = pack_bf16x2(v2, v3);
        float e00 = v0 - __uint_as_float(u0 << 16);
        float e01 = v1 - __uint_as_float(u0 & 0xFFFF0000u);
        float e10 = v2 - __uint_as_float(u1 << 16);
        float e11 = v3 - __uint_as_float(u1 & 0xFFFF0000u);
        *(uint32_t*)(Oh + a0) = u0;
        *(uint32_t*)(Oh + a1) = u1;
        *(uint32_t*)(Ol + a0) = pack_bf16x2(e00, e01);
        *(uint32_t*)(Ol + a1) = pack_bf16x2(e10, e11);
    }
}

// ---------------------------------------------------------------------------
extern "C" void kernel_launch(void* const* d_in, const int* in_sizes, int n_in,
                              void* d_out, int out_size)
{
    const float* query = (const float*)d_in[0];
    const float* key   = (const float*)d_in[1];
    const float* value = (const float*)d_in[2];
    const float* Wq    = (const float*)d_in[3];
    const float* bq    = (const float*)d_in[4];
    const float* Wk    = (const float*)d_in[5];
    const float* bk    = (const float*)d_in[6];
    const float* Wv    = (const float*)d_in[7];
    const float* bv    = (const float*)d_in[8];
    const float* Wo    = (const float*)d_in[9];
    const float* bo    = (const float*)d_in[10];
    float* out = (float*)d_out;

    __nv_bfloat16 *pQh, *pQl, *pKh, *pKl, *pVh, *pVl;
    __nv_bfloat16 *paQh, *paQl, *paKh, *paKl, *paVh, *paVl;
    __nv_bfloat16 *pwQh, *pwQl, *pwKh, *pwKl, *pwVh, *pwVl, *pwOh, *pwOl;
    cudaGetSymbolAddress((void**)&pQh, g_Qh);
    cudaGetSymbolAddress((void**)&pQl, g_Ql);
    cudaGetSymbolAddress((void**)&pKh, g_Kh);
    cudaGetSymbolAddress((void**)&pKl, g_Kl);
    cudaGetSymbolAddress((void**)&pVh, g_Vh);
    cudaGetSymbolAddress((void**)&pVl, g_Vl);
    cudaGetSymbolAddress((void**)&paQh, g_aQh);
    cudaGetSymbolAddress((void**)&paQl, g_aQl);
    cudaGetSymbolAddress((void**)&paKh, g_aKh);
    cudaGetSymbolAddress((void**)&paKl, g_aKl);
    cudaGetSymbolAddress((void**)&paVh, g_aVh);
    cudaGetSymbolAddress((void**)&paVl, g_aVl);
    cudaGetSymbolAddress((void**)&pwQh, g_wQh);
    cudaGetSymbolAddress((void**)&pwQl, g_wQl);
    cudaGetSymbolAddress((void**)&pwKh, g_wKh);
    cudaGetSymbolAddress((void**)&pwKl, g_wKl);
    cudaGetSymbolAddress((void**)&pwVh, g_wVh);
    cudaGetSymbolAddress((void**)&pwVl, g_wVl);
    cudaGetSymbolAddress((void**)&pwOh, g_wOh);
    cudaGetSymbolAddress((void**)&pwOl, g_wOl);

    cudaFuncSetAttribute(gemm_mma, cudaFuncAttributeMaxDynamicSharedMemorySize,
                         GEMM_SMEM);
    cudaFuncSetAttribute(flash_mma, cudaFuncAttributeMaxDynamicSharedMemorySize,
                         FLASH_SMEM);

    const int nA4 = M_ * D_ / 4;   // 1M float4
    const int nW4 = D_ * D_ / 4;   // 256K float4

    // 1) all splits in one launch
    SJobs sj;
    sj.src[0] = query; sj.hi[0] = paQh; sj.lo[0] = paQl; sj.n4[0] = nA4;
    sj.src[1] = key;   sj.hi[1] = paKh; sj.lo[1] = paKl; sj.n4[1] = nA4;
    sj.src[2] = value; sj.hi[2] = paVh; sj.lo[2] = paVl; sj.n4[2] = nA4;
    sj.src[3] = Wq;    sj.hi[3] = pwQh; sj.lo[3] = pwQl; sj.n4[3] = nW4;
    sj.src[4] = Wk;    sj.hi[4] = pwKh; sj.lo[4] = pwKl; sj.n4[4] = nW4;
    sj.src[5] = Wv;    sj.hi[5] = pwVh; sj.lo[5] = pwVl; sj.n4[5] = nW4;
    sj.src[6] = Wo;    sj.hi[6] = pwOh; sj.lo[6] = pwOl; sj.n4[6] = nW4;
    split_all<<<dim3(1024, 7), 256>>>(sj);

    // 2) fused Q/K/V projection GEMMs
    GJobs gq;
    gq.j[0] = GJob{paQh, paQl, pwQh, pwQl, bq, nullptr, pQh, pQl, 1, 0.125f};
    gq.j[1] = GJob{paKh, paKl, pwKh, pwKl, bk, nullptr, pKh, pKl, 1, 1.0f};
    gq.j[2] = GJob{paVh, paVl, pwVh, pwVl, bv, nullptr, pVh, pVl, 2, 1.0f};
    gemm_mma<<<dim3(D_ / 128, M_ / 128, 3), 256, GEMM_SMEM>>>(gq);

    // 3) attention (writes split O into paQh/paQl — activations are dead now)
    flash_mma<<<dim3(S_ / 128, B_ * H_), 256, FLASH_SMEM>>>(
        pQh, pQl, pKh, pKl, pVh, pVl, paQh, paQl);

    // 4) O projection -> fp32 out
    GJobs go;
    go.j[0] = GJob{paQh, paQl, pwOh, pwOl, bo, out, nullptr, nullptr, 0, 1.0f};
    go.j[1] = go.j[0];
    go.j[2] = go.j[0];
    gemm_mma<<<dim3(D_ / 128, M_ / 128, 1), 256, GEMM_SMEM>>>(go);
}

// round 12
// speedup vs baseline: 3.9253x; 1.0551x over previous
#include <cuda_runtime.h>
#include <cuda_bf16.h>
#include <cstdint>
#include <math.h>

#define B_  2
#define S_  2048
#define D_  1024
#define H_  16
#define DK_ 64
#define M_  (B_ * S_)

// Scratch (allocation-free rule: __device__ globals)
__device__ __nv_bfloat16 g_Qh[M_ * D_];
__device__ __nv_bfloat16 g_Ql[M_ * D_];
__device__ __nv_bfloat16 g_Kh[M_ * D_];
__device__ __nv_bfloat16 g_Kl[M_ * D_];
__device__ __nv_bfloat16 g_Vh[M_ * D_];   // transposed [B,H,64,S]
__device__ __nv_bfloat16 g_Vl[M_ * D_];
// activation splits (query/key/value); aQ reused as flash O output
__device__ __nv_bfloat16 g_aQh[M_ * D_];
__device__ __nv_bfloat16 g_aQl[M_ * D_];
__device__ __nv_bfloat16 g_aKh[M_ * D_];
__device__ __nv_bfloat16 g_aKl[M_ * D_];
__device__ __nv_bfloat16 g_aVh[M_ * D_];
__device__ __nv_bfloat16 g_aVl[M_ * D_];
// weight splits
__device__ __nv_bfloat16 g_wQh[D_ * D_];
__device__ __nv_bfloat16 g_wQl[D_ * D_];
__device__ __nv_bfloat16 g_wKh[D_ * D_];
__device__ __nv_bfloat16 g_wKl[D_ * D_];
__device__ __nv_bfloat16 g_wVh[D_ * D_];
__device__ __nv_bfloat16 g_wVl[D_ * D_];
__device__ __nv_bfloat16 g_wOh[D_ * D_];
__device__ __nv_bfloat16 g_wOl[D_ * D_];

// ---------------------------------------------------------------------------
__device__ __forceinline__ uint32_t smem_u32(const void* p) {
    return (uint32_t)__cvta_generic_to_shared(p);
}

#define CP_ASYNC16(dst_u32, src_ptr) \
    asm volatile("cp.async.cg.shared.global [%0], [%1], 16;" :: "r"(dst_u32), "l"(src_ptr))
#define CP_COMMIT() asm volatile("cp.async.commit_group;")
#define CP_WAIT(n)  asm volatile("cp.async.wait_group %0;" :: "n"(n) : "memory")

#define LDSM4(r, addr) asm volatile( \
    "ldmatrix.sync.aligned.m8n8.x4.shared.b16 {%0,%1,%2,%3}, [%4];" \
    : "=r"((r)[0]), "=r"((r)[1]), "=r"((r)[2]), "=r"((r)[3]) : "r"(addr))

#define MMA16816(d, a, b) asm volatile( \
    "mma.sync.aligned.m16n8k16.row.col.f32.bf16.bf16.f32 " \
    "{%0,%1,%2,%3}, {%4,%5,%6,%7}, {%8,%9}, {%0,%1,%2,%3};" \
    : "+f"((d)[0]), "+f"((d)[1]), "+f"((d)[2]), "+f"((d)[3]) \
    : "r"((a)[0]), "r"((a)[1]), "r"((a)[2]), "r"((a)[3]), \
      "r"((b)[0]), "r"((b)[1]))

__device__ __forceinline__ uint32_t pack_bf16x2(float lo, float hi) {
    uint32_t r;
    asm("cvt.rn.bf16x2.f32 %0, %1, %2;" : "=r"(r) : "f"(hi), "f"(lo));
    return r;
}

// ---------------------------------------------------------------------------
// fused fp32 -> bf16 hi/lo split for all 7 tensors, 4 float4 per thread
// ---------------------------------------------------------------------------
struct SJobs {
    const float* src[7];
    __nv_bfloat16* hi[7];
    __nv_bfloat16* lo[7];
    int n4[7];
};

__global__ __launch_bounds__(256) void split_all(SJobs s)
{
    const int z = blockIdx.y;
    const int n4 = s.n4[z];
    const float* __restrict__ x = s.src[z];
    __nv_bfloat16* __restrict__ hi = s.hi[z];
    __nv_bfloat16* __restrict__ lo = s.lo[z];

    int i0 = blockIdx.x * 1024 + threadIdx.x;
    if (i0 >= n4) return;
#pragma unroll
    for (int j = 0; j < 4; j++) {
        int i = i0 + j * 256;
        if (i < n4) {
            float4 v = ((const float4*)x)[i];
            uint32_t h0 = pack_bf16x2(v.x, v.y);
            uint32_t h1 = pack_bf16x2(v.z, v.w);
            float r0 = v.x - __uint_as_float(h0 << 16);
            float r1 = v.y - __uint_as_float(h0 & 0xFFFF0000u);
            float r2 = v.z - __uint_as_float(h1 << 16);
            float r3 = v.w - __uint_as_float(h1 & 0xFFFF0000u);
            ((uint2*)hi)[i] = make_uint2(h0, h1);
            ((uint2*)lo)[i] = make_uint2(pack_bf16x2(r0, r1), pack_bf16x2(r2, r3));
        }
    }
}

// ---------------------------------------------------------------------------
// HMMA bf16-split GEMM, multi-job (grid.z selects job). Unchanged from R11.
// ---------------------------------------------------------------------------
#define GSTAGES 3
#define GSTAGE_BYTES 32768
#define GEMM_SMEM (GSTAGES * GSTAGE_BYTES)

struct GJob {
    const __nv_bfloat16 *Xh, *Xl, *Wh, *Wl;
    const float* bias;
    float* outf;
    __nv_bfloat16 *oh, *ol;
    int mode;
    float scale;
};
struct GJobs { GJob j[3]; };

__global__ __launch_bounds__(256) void gemm_mma(GJobs jobs)
{
    extern __shared__ char sb[];
    const GJob jb = jobs.j[blockIdx.z];
    const __nv_bfloat16* __restrict__ Xh = jb.Xh;
    const __nv_bfloat16* __restrict__ Xl = jb.Xl;
    const __nv_bfloat16* __restrict__ Wh = jb.Wh;
    const __nv_bfloat16* __restrict__ Wl = jb.Wl;

    const int t = threadIdx.x, l = t & 31, wid = t >> 5;
    const int m0 = blockIdx.y * 128, n0 = blockIdx.x * 128;
    const int wm = wid >> 2, wn = wid & 3;

    const int arow = l & 15;
    const int ak8  = (l >> 4) & 1;
    const uint32_t axor = (uint32_t)((arow & 6) << 3);
    const int brow = (l & 7) + ((l >> 4) & 1) * 8;
    const int bk8  = (l >> 3) & 1;
    const uint32_t bxor = (uint32_t)((brow & 6) << 3);

    const uint32_t sbase = smem_u32(sb);

    float acc[4][4][4];
#pragma unroll
    for (int a = 0; a < 4; a++)
#pragma unroll
        for (int b = 0; b < 4; b++)
#pragma unroll
            for (int c = 0; c < 4; c++) acc[a][b][c] = 0.f;

#define GEMM_ISSUE(cc) do {                                                   \
    int _c = (cc);                                                            \
    uint32_t st = sbase + (uint32_t)((_c % GSTAGES) * GSTAGE_BYTES);          \
    int kc = _c * 32;                                                         \
    _Pragma("unroll")                                                         \
    for (int j = 0; j < 8; j++) {                                             \
        int idx = j * 256 + t;                                                \
        int half = idx >> 9;                                                  \
        int e = idx & 511;                                                    \
        int row = e >> 2;                                                     \
        uint32_t coff = (uint32_t)((e & 3) * 16);                             \
        uint32_t dst = st + (uint32_t)(half * 8192 + row * 64) +              \
                       (coff ^ ((uint32_t)(row & 6) << 3));                   \
        const __nv_bfloat16* src =                                            \
            half == 0 ? Xh + (size_t)(m0 + row) * D_ + kc + (e & 3) * 8 :     \
            half == 1 ? Xl + (size_t)(m0 + row) * D_ + kc + (e & 3) * 8 :     \
            half == 2 ? Wh + (size_t)(n0 + row) * D_ + kc + (e & 3) * 8 :     \
                        Wl + (size_t)(n0 + row) * D_ + kc + (e & 3) * 8;      \
        CP_ASYNC16(dst, src);                                                 \
    }                                                                         \
    CP_COMMIT();                                                              \
} while (0)

    GEMM_ISSUE(0);
    GEMM_ISSUE(1);

    const uint32_t aoffbase = (uint32_t)((wm * 64 + arow) * 64);
    const uint32_t boffbase = (uint32_t)((wn * 32 + brow) * 64);

    for (int c = 0; c < 32; c++) {
        CP_WAIT(1);
        __syncthreads();
        uint32_t Ah = sbase + (uint32_t)((c % GSTAGES) * GSTAGE_BYTES);
        uint32_t Al = Ah + 8192;
        uint32_t Bh = Ah + 16384;
        uint32_t Bl = Ah + 24576;

#pragma unroll
        for (int ks = 0; ks < 2; ks++) {
            uint32_t coffA = (uint32_t)(ks * 32 + ak8 * 16);
            uint32_t coffB = (uint32_t)(ks * 32 + bk8 * 16);
            uint32_t bh[8], bl[8];
#pragma unroll
            for (int nx = 0; nx < 2; nx++) {
                uint32_t off = boffbase + (uint32_t)(nx * 1024) + (coffB ^ bxor);
                LDSM4(&bh[nx * 4], Bh + off);
                LDSM4(&bl[nx * 4], Bl + off);
            }
#pragma unroll
            for (int mi = 0; mi < 4; mi++) {
                uint32_t offa = aoffbase + (uint32_t)(mi * 1024) + (coffA ^ axor);
                uint32_t ah[4], al[4];
                LDSM4(ah, Ah + offa);
                LDSM4(al, Al + offa);
#pragma unroll
                for (int ni = 0; ni < 4; ni++) {
                    MMA16816(acc[mi][ni], ah, &bh[ni * 2]);
                    MMA16816(acc[mi][ni], ah, &bl[ni * 2]);
                    MMA16816(acc[mi][ni], al, &bh[ni * 2]);
                }
            }
        }
        if (c + 2 < 32) GEMM_ISSUE(c + 2);
    }
    CP_WAIT(0);

    const int mode = jb.mode;
    const float scale = jb.scale;
#pragma unroll
    for (int mi = 0; mi < 4; mi++) {
        int r0 = m0 + wm * 64 + mi * 16 + (l >> 2);
#pragma unroll
        for (int ni = 0; ni < 4; ni++) {
            int col = n0 + wn * 32 + ni * 8 + (l & 3) * 2;
            float2 bv = *(const float2*)&jb.bias[col];
            float v00 = acc[mi][ni][0] + bv.x, v01 = acc[mi][ni][1] + bv.y;
            float v10 = acc[mi][ni][2] + bv.x, v11 = acc[mi][ni][3] + bv.y;
            if (mode == 0) {
                *(float2*)&jb.outf[(size_t)r0 * D_ + col] = make_float2(v00, v01);
                *(float2*)&jb.outf[(size_t)(r0 + 8) * D_ + col] = make_float2(v10, v11);
            } else {
                v00 *= scale; v01 *= scale; v10 *= scale; v11 *= scale;
                int hh = col >> 6, d = col & 63;
#pragma unroll
                for (int rr = 0; rr < 2; rr++) {
                    int r = r0 + rr * 8;
                    float a0 = rr ? v10 : v00, a1 = rr ? v11 : v01;
                    int bb = r >> 11, s = r & 2047;
                    uint32_t ph = pack_bf16x2(a0, a1);
                    float e0 = a0 - __uint_as_float(ph << 16);
                    float e1 = a1 - __uint_as_float(ph & 0xFFFF0000u);
                    uint32_t pl = pack_bf16x2(e0, e1);
                    if (mode == 1) {
                        size_t a = ((size_t)(bb * H_ + hh) * S_ + s) * 64 + d;
                        *(uint32_t*)(jb.oh + a) = ph;
                        *(uint32_t*)(jb.ol + a) = pl;
                    } else {
                        size_t a = ((size_t)(bb * H_ + hh) * 64 + d) * (size_t)S_ + s;
                        jb.oh[a]      = __ushort_as_bfloat16((unsigned short)(ph & 0xFFFF));
                        jb.oh[a + S_] = __ushort_as_bfloat16((unsigned short)(ph >> 16));
                        jb.ol[a]      = __ushort_as_bfloat16((unsigned short)(pl & 0xFFFF));
                        jb.ol[a + S_] = __ushort_as_bfloat16((unsigned short)(pl >> 16));
                    }
                }
            }
        }
    }
}

// ---------------------------------------------------------------------------
// HMMA flash attention, 128 threads / 64 q-rows per CTA, 3 CTAs/SM.
// Q staged through stage buffer 0, then register-resident.
// 2 stages x 32KB (Kh|Kl|Vh|Vl), one __syncthreads per tile.
// ---------------------------------------------------------------------------
#define FLASH_SMEM 65536

__global__ __launch_bounds__(128, 3) void flash_mma(
    const __nv_bfloat16* __restrict__ Qh, const __nv_bfloat16* __restrict__ Ql,
    const __nv_bfloat16* __restrict__ Kh, const __nv_bfloat16* __restrict__ Kl,
    const __nv_bfloat16* __restrict__ Vh, const __nv_bfloat16* __restrict__ Vl,
    __nv_bfloat16* __restrict__ Oh, __nv_bfloat16* __restrict__ Ol)
{
    extern __shared__ char sb[];
    const int t = threadIdx.x, l = t & 31, w = t >> 5;       // 4 warps
    const int bh = blockIdx.y, b = bh >> 4, h = bh & 15;
    const int qb = (int)(gridDim.x - 1 - blockIdx.x) * 64;   // heavy CTAs first

    const uint32_t sbase = smem_u32(sb);
    const size_t base = (size_t)bh * S_ * 64;

    const int arow = l & 15;
    const int ak8  = (l >> 4) & 1;
    const int brow = (l & 7) + ((l >> 4) & 1) * 8;
    const int bk8  = (l >> 3) & 1;

    // ---- stage Q (64x64 hi+lo = 16KB) through stage buffer 0 ----
#pragma unroll
    for (int it = 0; it < 8; it++) {
        int idx = it * 128 + t;          // 1024 16B-copies
        int mat = idx >> 9;              // 0 Qh, 1 Ql
        int r   = (idx >> 3) & 63;
        int c   = idx & 7;
        const __nv_bfloat16* src = (mat ? Ql : Qh) + base + (size_t)(qb + r) * 64 + c * 8;
        uint32_t dst = sbase + (uint32_t)(mat * 8192 + r * 128 + ((c ^ (r & 7)) * 16));
        CP_ASYNC16(dst, src);
    }
    CP_COMMIT();
    CP_WAIT(0);
    __syncthreads();

    // ---- Q fragments to registers ----
    uint32_t qhA[4][4], qlA[4][4];
    {
        int qrow = w * 16 + arow;        // < 64
        uint32_t rbase = sbase + (uint32_t)(qrow * 128);
#pragma unroll
        for (int kc = 0; kc < 4; kc++) {
            uint32_t off = (uint32_t)(((kc * 2 + ak8) ^ (qrow & 7)) * 16);
            LDSM4(qhA[kc], rbase + off);
            LDSM4(qlA[kc], rbase + 8192 + off);
        }
    }
    __syncthreads();    // all warps done reading Q before stage 0 is reused

#define FLASH_ISSUE(kt_) do {                                                 \
    int _key0 = (kt_) * 64;                                                   \
    uint32_t _st = sbase + (uint32_t)(((kt_) & 1) * 32768);                   \
    _Pragma("unroll")                                                         \
    for (int it = 0; it < 16; it++) {                                         \
        int idx = it * 128 + t;                                               \
        int mat = idx >> 9;                                                   \
        int r   = (idx >> 3) & 63;                                            \
        int c   = idx & 7;                                                    \
        const __nv_bfloat16* src;                                             \
        if      (mat == 0) src = Kh + base + (size_t)(_key0 + r) * 64 + c * 8;\
        else if (mat == 1) src = Kl + base + (size_t)(_key0 + r) * 64 + c * 8;\
        else if (mat == 2) src = Vh + base + (size_t)r * S_ + _key0 + c * 8;  \
        else               src = Vl + base + (size_t)r * S_ + _key0 + c * 8;  \
        uint32_t dst = _st + (uint32_t)(mat * 8192 + r * 128 + ((c ^ (r & 7)) * 16)); \
        CP_ASYNC16(dst, src);                                                 \
    }                                                                         \
    CP_COMMIT();                                                              \
} while (0)

    FLASH_ISSUE(0);

    float O[8][4];
#pragma unroll
    for (int d = 0; d < 8; d++)
#pragma unroll
        for (int c = 0; c < 4; c++) O[d][c] = 0.f;
    float m0 = -1e30f, m1 = -1e30f, l0 = 0.f, l1 = 0.f;

    const int wmin = qb + w * 16;
    const int r0l  = wmin + (l >> 2);
    const int nt   = qb / 64 + 1;        // all tiles needed by every warp

    for (int kt = 0; kt < nt; kt++) {
        CP_WAIT(0);
        __syncthreads();                 // tile kt ready; all warps past kt-1
        if (kt + 1 < nt) FLASH_ISSUE(kt + 1);

        const int key0 = kt * 64;
        uint32_t st = sbase + (uint32_t)((kt & 1) * 32768);

        // ---- S = Q K^T (3-term split) ----
        float S[8][4];
#pragma unroll
        for (int nf = 0; nf < 8; nf++)
#pragma unroll
            for (int c = 0; c < 4; c++) S[nf][c] = 0.f;

#pragma unroll
        for (int kc = 0; kc < 4; kc++) {
            uint32_t kbh[16], kbl[16];
#pragma unroll
            for (int g = 0; g < 4; g++) {
                int row = g * 16 + brow;
                uint32_t off = (uint32_t)(row * 128 + (((kc * 2 + bk8) ^ (row & 7)) * 16));
                LDSM4(&kbh[g * 4], st + off);
                LDSM4(&kbl[g * 4], st + 8192 + off);
            }
#pragma unroll
            for (int nf = 0; nf < 8; nf++) {
                int ix = (nf >> 1) * 4 + (nf & 1) * 2;
                MMA16816(S[nf], qhA[kc], &kbh[ix]);
                MMA16816(S[nf], qhA[kc], &kbl[ix]);
                MMA16816(S[nf], qlA[kc], &kbh[ix]);
            }
        }

        // ---- causal mask (diagonal tile only) ----
        if (key0 + 63 > wmin) {
#pragma unroll
            for (int nf = 0; nf < 8; nf++) {
                int k0 = key0 + nf * 8 + (l & 3) * 2;
                if (k0     > r0l)     S[nf][0] = -1e30f;
                if (k0 + 1 > r0l)     S[nf][1] = -1e30f;
                if (k0     > r0l + 8) S[nf][2] = -1e30f;
                if (k0 + 1 > r0l + 8) S[nf][3] = -1e30f;
            }
        }

        // ---- online softmax ----
        float mx0 = -1e30f, mx1 = -1e30f;
#pragma unroll
        for (int nf = 0; nf < 8; nf++) {
            mx0 = fmaxf(mx0, fmaxf(S[nf][0], S[nf][1]));
            mx1 = fmaxf(mx1, fmaxf(S[nf][2], S[nf][3]));
        }
        mx0 = fmaxf(mx0, __shfl_xor_sync(0xFFFFFFFF, mx0, 1));
        mx0 = fmaxf(mx0, __shfl_xor_sync(0xFFFFFFFF, mx0, 2));
        mx1 = fmaxf(mx1, __shfl_xor_sync(0xFFFFFFFF, mx1, 1));
        mx1 = fmaxf(mx1, __shfl_xor_sync(0xFFFFFFFF, mx1, 2));

        float mn0 = fmaxf(m0, mx0), mn1 = fmaxf(m1, mx1);
        float al0 = __expf(m0 - mn0), al1 = __expf(m1 - mn1);
        m0 = mn0; m1 = mn1;

        uint32_t pha[4][4], pla[4][4];
        float rs0 = 0.f, rs1 = 0.f;
#pragma unroll
        for (int nf = 0; nf < 8; nf++) {
            float p00 = __expf(S[nf][0] - mn0);
            float p01 = __expf(S[nf][1] - mn0);
            float p10 = __expf(S[nf][2] - mn1);
            float p11 = __expf(S[nf][3] - mn1);
            rs0 += p00 + p01; rs1 += p10 + p11;
            int kc = nf >> 1, a0 = (nf & 1) * 2;
            uint32_t u0 = pack_bf16x2(p00, p01);
            uint32_t u1 = pack_bf16x2(p10, p11);
            pha[kc][a0]     = u0;
            pha[kc][a0 + 1] = u1;
            float e00 = p00 - __uint_as_float(u0 << 16);
            float e01 = p01 - __uint_as_float(u0 & 0xFFFF0000u);
            float e10 = p10 - __uint_as_float(u1 << 16);
            float e11 = p11 - __uint_as_float(u1 & 0xFFFF0000u);
            pla[kc][a0]     = pack_bf16x2(e00, e01);
            pla[kc][a0 + 1] = pack_bf16x2(e10, e11);
        }
        rs0 += __shfl_xor_sync(0xFFFFFFFF, rs0, 1);
        rs0 += __shfl_xor_sync(0xFFFFFFFF, rs0, 2);
        rs1 += __shfl_xor_sync(0xFFFFFFFF, rs1, 1);
        rs1 += __shfl_xor_sync(0xFFFFFFFF, rs1, 2);
        l0 = l0 * al0 + rs0;
        l1 = l1 * al1 + rs1;

#pragma unroll
        for (int d = 0; d < 8; d++) {
            O[d][0] *= al0; O[d][1] *= al0;
            O[d][2] *= al1; O[d][3] *= al1;
        }

        // ---- O += P V (3-term split) ----
#pragma unroll
        for (int kc = 0; kc < 4; kc++) {
            uint32_t vbh[16], vbl[16];
#pragma unroll
            for (int g = 0; g < 4; g++) {
                int row = g * 16 + brow;
                uint32_t off = (uint32_t)(row * 128 + (((kc * 2 + bk8) ^ (row & 7)) * 16));
                LDSM4(&vbh[g * 4], st + 16384 + off);
                LDSM4(&vbl[g * 4], st + 24576 + off);
            }
#pragma unroll
            for (int df = 0; df < 8; df++) {
                int ix = (df >> 1) * 4 + (df & 1) * 2;
                MMA16816(O[df], pha[kc], &vbh[ix]);
                MMA16816(O[df], pha[kc], &vbl[ix]);
                MMA16816(O[df], pla[kc], &vbh[ix]);
            }
        }
    }

    // ---- write O bf16 split to [M, D] layout ----
    const float inv0 = 1.f / l0, inv1 = 1.f / l1;
    const int r0g = qb + w * 16 + (l >> 2);
#pragma unroll
    for (int df = 0; df < 8; df++) {
        int d = df * 8 + (l & 3) * 2;
        float v0 = O[df][0] * inv0, v1 = O[df][1] * inv0;
        float v2 = O[df][2] * inv1, v3 = O[df][3] * inv1;
        size_t a0 = ((size_t)(b * S_ + r0g)) * D_ + h * 64 + d;
        size_t a1 = ((size_t)(b * S_ + r0g + 8)) * D_ + h * 64 + d;
        uint32_t u0 = pack_bf16x2(v0, v1);
        uint32_t u1 = pack_bf16x2(v2, v3);
        float e00 = v0 - __uint_as_float(u0 << 16);
        float e01 = v1 - __uint_as_float(u0 & 0xFFFF0000u);
        float e10 = v2 - __uint_as_float(u1 << 16);
        float e11 = v3 - __uint_as_float(u1 & 0xFFFF0000u);
        *(uint32_t*)(Oh + a0) = u0;
        *(uint32_t*)(Oh + a1) = u1;
        *(uint32_t*)(Ol + a0) = pack_bf16x2(e00, e01);
        *(uint32_t*)(Ol + a1) = pack_bf16x2(e10, e11);
    }
}

// ---------------------------------------------------------------------------
extern "C" void kernel_launch(void* const* d_in, const int* in_sizes, int n_in,
                              void* d_out, int out_size)
{
    const float* query = (const float*)d_in[0];
    const float* key   = (const float*)d_in[1];
    const float* value = (const float*)d_in[2];
    const float* Wq    = (const float*)d_in[3];
    const float* bq    = (const float*)d_in[4];
    const float* Wk    = (const float*)d_in[5];
    const float* bk    = (const float*)d_in[6];
    const float* Wv    = (const float*)d_in[7];
    const float* bv    = (const float*)d_in[8];
    const float* Wo    = (const float*)d_in[9];
    const float* bo    = (const float*)d_in[10];
    float* out = (float*)d_out;

    __nv_bfloat16 *pQh, *pQl, *pKh, *pKl, *pVh, *pVl;
    __nv_bfloat16 *paQh, *paQl, *paKh, *paKl, *paVh, *paVl;
    __nv_bfloat16 *pwQh, *pwQl, *pwKh, *pwKl, *pwVh, *pwVl, *pwOh, *pwOl;
    cudaGetSymbolAddress((void**)&pQh, g_Qh);
    cudaGetSymbolAddress((void**)&pQl, g_Ql);
    cudaGetSymbolAddress((void**)&pKh, g_Kh);
    cudaGetSymbolAddress((void**)&pKl, g_Kl);
    cudaGetSymbolAddress((void**)&pVh, g_Vh);
    cudaGetSymbolAddress((void**)&pVl, g_Vl);
    cudaGetSymbolAddress((void**)&paQh, g_aQh);
    cudaGetSymbolAddress((void**)&paQl, g_aQl);
    cudaGetSymbolAddress((void**)&paKh, g_aKh);
    cudaGetSymbolAddress((void**)&paKl, g_aKl);
    cudaGetSymbolAddress((void**)&paVh, g_aVh);
    cudaGetSymbolAddress((void**)&paVl, g_aVl);
    cudaGetSymbolAddress((void**)&pwQh, g_wQh);
    cudaGetSymbolAddress((void**)&pwQl, g_wQl);
    cudaGetSymbolAddress((void**)&pwKh, g_wKh);
    cudaGetSymbolAddress((void**)&pwKl, g_wKl);
    cudaGetSymbolAddress((void**)&pwVh, g_wVh);
    cudaGetSymbolAddress((void**)&pwVl, g_wVl);
    cudaGetSymbolAddress((void**)&pwOh, g_wOh);
    cudaGetSymbolAddress((void**)&pwOl, g_wOl);

    cudaFuncSetAttribute(gemm_mma, cudaFuncAttributeMaxDynamicSharedMemorySize,
                         GEMM_SMEM);
    cudaFuncSetAttribute(flash_mma, cudaFuncAttributeMaxDynamicSharedMemorySize,
                         FLASH_SMEM);

    const int nA4 = M_ * D_ / 4;
    const int nW4 = D_ * D_ / 4;

    // 1) all splits in one launch
    SJobs sj;
    sj.src[0] = query; sj.hi[0] = paQh; sj.lo[0] = paQl; sj.n4[0] = nA4;
    sj.src[1] = key;   sj.hi[1] = paKh; sj.lo[1] = paKl; sj.n4[1] = nA4;
    sj.src[2] = value; sj.hi[2] = paVh; sj.lo[2] = paVl; sj.n4[2] = nA4;
    sj.src[3] = Wq;    sj.hi[3] = pwQh; sj.lo[3] = pwQl; sj.n4[3] = nW4;
    sj.src[4] = Wk;    sj.hi[4] = pwKh; sj.lo[4] = pwKl; sj.n4[4] = nW4;
    sj.src[5] = Wv;    sj.hi[5] = pwVh; sj.lo[5] = pwVl; sj.n4[5] = nW4;
    sj.src[6] = Wo;    sj.hi[6] = pwOh; sj.lo[6] = pwOl; sj.n4[6] = nW4;
    split_all<<<dim3(1024, 7), 256>>>(sj);

    // 2) fused Q/K/V projection GEMMs
    GJobs gq;
    gq.j[0] = GJob{paQh, paQl, pwQh, pwQl, bq, nullptr, pQh, pQl, 1, 0.125f};
    gq.j[1] = GJob{paKh, paKl, pwKh, pwKl, bk, nullptr, pKh, pKl, 1, 1.0f};
    gq.j[2] = GJob{paVh, paVl, pwVh, pwVl, bv, nullptr, pVh, pVl, 2, 1.0f};
    gemm_mma<<<dim3(D_ / 128, M_ / 128, 3), 256, GEMM_SMEM>>>(gq);

    // 3) attention (writes split O into paQh/paQl)
    flash_mma<<<dim3(S_ / 64, B_ * H_), 128, FLASH_SMEM>>>(
        pQh, pQl, pKh, pKl, pVh, pVl, paQh, paQl);

    // 4) O projection -> fp32 out
    GJobs go;
    go.j[0] = GJob{paQh, paQl, pwOh, pwOl, bo, out, nullptr, nullptr, 0, 1.0f};
    go.j[1] = go.j[0];
    go.j[2] = go.j[0];
    gemm_mma<<<dim3(D_ / 128, M_ / 128, 1), 256, GEMM_SMEM>>>(go);
}

// round 13
// speedup vs baseline: 4.8085x; 1.2250x over previous
#include <cuda_runtime.h>
#include <cuda_bf16.h>
#include <cuda_fp16.h>
#include <cstdint>
#include <math.h>

#define B_  2
#define S_  2048
#define D_  1024
#define H_  16
#define DK_ 64
#define M_  (B_ * S_)

// Scratch (allocation-free rule: __device__ globals)
__device__ __nv_bfloat16 g_Qh[M_ * D_];
__device__ __nv_bfloat16 g_Ql[M_ * D_];
__device__ __nv_bfloat16 g_Kh[M_ * D_];
__device__ __nv_bfloat16 g_Kl[M_ * D_];
__device__ __half        g_V16[M_ * D_];  // transposed [B,H,64,S], single fp16
// activation splits (query/key/value); aQ reused as flash O output (fp16)
__device__ __nv_bfloat16 g_aQh[M_ * D_];
__device__ __nv_bfloat16 g_aQl[M_ * D_];
__device__ __nv_bfloat16 g_aKh[M_ * D_];
__device__ __nv_bfloat16 g_aKl[M_ * D_];
__device__ __nv_bfloat16 g_aVh[M_ * D_];
__device__ __nv_bfloat16 g_aVl[M_ * D_];
// weight splits (Wq/Wk/Wv bf16 split; Wo single fp16)
__device__ __nv_bfloat16 g_wQh[D_ * D_];
__device__ __nv_bfloat16 g_wQl[D_ * D_];
__device__ __nv_bfloat16 g_wKh[D_ * D_];
__device__ __nv_bfloat16 g_wKl[D_ * D_];
__device__ __nv_bfloat16 g_wVh[D_ * D_];
__device__ __nv_bfloat16 g_wVl[D_ * D_];
__device__ __half        g_wO16[D_ * D_];

// ---------------------------------------------------------------------------
__device__ __forceinline__ uint32_t smem_u32(const void* p) {
    return (uint32_t)__cvta_generic_to_shared(p);
}

#define CP_ASYNC16(dst_u32, src_ptr) \
    asm volatile("cp.async.cg.shared.global [%0], [%1], 16;" :: "r"(dst_u32), "l"(src_ptr))
#define CP_COMMIT() asm volatile("cp.async.commit_group;")
#define CP_WAIT(n)  asm volatile("cp.async.wait_group %0;" :: "n"(n) : "memory")

#define LDSM4(r, addr) asm volatile( \
    "ldmatrix.sync.aligned.m8n8.x4.shared.b16 {%0,%1,%2,%3}, [%4];" \
    : "=r"((r)[0]), "=r"((r)[1]), "=r"((r)[2]), "=r"((r)[3]) : "r"(addr))

#define MMA16816(d, a, b) asm volatile( \
    "mma.sync.aligned.m16n8k16.row.col.f32.bf16.bf16.f32 " \
    "{%0,%1,%2,%3}, {%4,%5,%6,%7}, {%8,%9}, {%0,%1,%2,%3};" \
    : "+f"((d)[0]), "+f"((d)[1]), "+f"((d)[2]), "+f"((d)[3]) \
    : "r"((a)[0]), "r"((a)[1]), "r"((a)[2]), "r"((a)[3]), \
      "r"((b)[0]), "r"((b)[1]))

#define MMA16816H(d, a, b) asm volatile( \
    "mma.sync.aligned.m16n8k16.row.col.f32.f16.f16.f32 " \
    "{%0,%1,%2,%3}, {%4,%5,%6,%7}, {%8,%9}, {%0,%1,%2,%3};" \
    : "+f"((d)[0]), "+f"((d)[1]), "+f"((d)[2]), "+f"((d)[3]) \
    : "r"((a)[0]), "r"((a)[1]), "r"((a)[2]), "r"((a)[3]), \
      "r"((b)[0]), "r"((b)[1]))

__device__ __forceinline__ uint32_t pack_bf16x2(float lo, float hi) {
    uint32_t r;
    asm("cvt.rn.bf16x2.f32 %0, %1, %2;" : "=r"(r) : "f"(hi), "f"(lo));
    return r;
}
__device__ __forceinline__ uint32_t pack_f16x2(float lo, float hi) {
    uint32_t r;
    asm("cvt.rn.f16x2.f32 %0, %1, %2;" : "=r"(r) : "f"(hi), "f"(lo));
    return r;
}

// ---------------------------------------------------------------------------
// fused split: jobs 0-5 -> bf16 hi/lo split, job 6 (Wo) -> single fp16
// ---------------------------------------------------------------------------
struct SJobs {
    const float* src[7];
    void* hi[7];
    void* lo[7];
    int n4[7];
    int f16[7];
};

__global__ __launch_bounds__(256) void split_all(SJobs s)
{
    const int z = blockIdx.y;
    const int n4 = s.n4[z];
    const float* __restrict__ x = s.src[z];

    int i0 = blockIdx.x * 1024 + threadIdx.x;
    if (i0 >= n4) return;
    if (s.f16[z]) {
        uint2* __restrict__ hi = (uint2*)s.hi[z];
#pragma unroll
        for (int j = 0; j < 4; j++) {
            int i = i0 + j * 256;
            if (i < n4) {
                float4 v = ((const float4*)x)[i];
                hi[i] = make_uint2(pack_f16x2(v.x, v.y), pack_f16x2(v.z, v.w));
            }
        }
    } else {
        uint2* __restrict__ hi = (uint2*)s.hi[z];
        uint2* __restrict__ lo = (uint2*)s.lo[z];
#pragma unroll
        for (int j = 0; j < 4; j++) {
            int i = i0 + j * 256;
            if (i < n4) {
                float4 v = ((const float4*)x)[i];
                uint32_t h0 = pack_bf16x2(v.x, v.y);
                uint32_t h1 = pack_bf16x2(v.z, v.w);
                float r0 = v.x - __uint_as_float(h0 << 16);
                float r1 = v.y - __uint_as_float(h0 & 0xFFFF0000u);
                float r2 = v.z - __uint_as_float(h1 << 16);
                float r3 = v.w - __uint_as_float(h1 & 0xFFFF0000u);
                hi[i] = make_uint2(h0, h1);
                lo[i] = make_uint2(pack_bf16x2(r0, r1), pack_bf16x2(r2, r3));
            }
        }
    }
}

// ---------------------------------------------------------------------------
// HMMA bf16-split GEMM (3-term), multi-job. QKV projections.
// mode 1: bf16 split out to [B,H,S,64], val = (acc+bias)*scale   (Q, K)
// mode 2: single fp16 out to [B,H,64,S] (transposed), val = acc+bias  (V)
// ---------------------------------------------------------------------------
#define GSTAGES 3
#define GSTAGE_BYTES 32768
#define GEMM_SMEM (GSTAGES * GSTAGE_BYTES)

struct GJob {
    const __nv_bfloat16 *Xh, *Xl, *Wh, *Wl;
    const float* bias;
    __nv_bfloat16 *oh, *ol;
    int mode;
    float scale;
};
struct GJobs { GJob j[3]; };

__global__ __launch_bounds__(256) void gemm_mma(GJobs jobs)
{
    extern __shared__ char sb[];
    const GJob jb = jobs.j[blockIdx.z];
    const __nv_bfloat16* __restrict__ Xh = jb.Xh;
    const __nv_bfloat16* __restrict__ Xl = jb.Xl;
    const __nv_bfloat16* __restrict__ Wh = jb.Wh;
    const __nv_bfloat16* __restrict__ Wl = jb.Wl;

    const int t = threadIdx.x, l = t & 31, wid = t >> 5;
    const int m0 = blockIdx.y * 128, n0 = blockIdx.x * 128;
    const int wm = wid >> 2, wn = wid & 3;

    const int arow = l & 15;
    const int ak8  = (l >> 4) & 1;
    const uint32_t axor = (uint32_t)((arow & 6) << 3);
    const int brow = (l & 7) + ((l >> 4) & 1) * 8;
    const int bk8  = (l >> 3) & 1;
    const uint32_t bxor = (uint32_t)((brow & 6) << 3);

    const uint32_t sbase = smem_u32(sb);

    float acc[4][4][4];
#pragma unroll
    for (int a = 0; a < 4; a++)
#pragma unroll
        for (int b = 0; b < 4; b++)
#pragma unroll
            for (int c = 0; c < 4; c++) acc[a][b][c] = 0.f;

#define GEMM_ISSUE(cc) do {                                                   \
    int _c = (cc);                                                            \
    uint32_t st = sbase + (uint32_t)((_c % GSTAGES) * GSTAGE_BYTES);          \
    int kc = _c * 32;                                                         \
    _Pragma("unroll")                                                         \
    for (int j = 0; j < 8; j++) {                                             \
        int idx = j * 256 + t;                                                \
        int half = idx >> 9;                                                  \
        int e = idx & 511;                                                    \
        int row = e >> 2;                                                     \
        uint32_t coff = (uint32_t)((e & 3) * 16);                             \
        uint32_t dst = st + (uint32_t)(half * 8192 + row * 64) +              \
                       (coff ^ ((uint32_t)(row & 6) << 3));                   \
        const __nv_bfloat16* src =                                            \
            half == 0 ? Xh + (size_t)(m0 + row) * D_ + kc + (e & 3) * 8 :     \
            half == 1 ? Xl + (size_t)(m0 + row) * D_ + kc + (e & 3) * 8 :     \
            half == 2 ? Wh + (size_t)(n0 + row) * D_ + kc + (e & 3) * 8 :     \
                        Wl + (size_t)(n0 + row) * D_ + kc + (e & 3) * 8;      \
        CP_ASYNC16(dst, src);                                                 \
    }                                                                         \
    CP_COMMIT();                                                              \
} while (0)

    GEMM_ISSUE(0);
    GEMM_ISSUE(1);

    const uint32_t aoffbase = (uint32_t)((wm * 64 + arow) * 64);
    const uint32_t boffbase = (uint32_t)((wn * 32 + brow) * 64);

    for (int c = 0; c < 32; c++) {
        CP_WAIT(1);
        __syncthreads();
        uint32_t Ah = sbase + (uint32_t)((c % GSTAGES) * GSTAGE_BYTES);
        uint32_t Al = Ah + 8192;
        uint32_t Bh = Ah + 16384;
        uint32_t Bl = Ah + 24576;

#pragma unroll
        for (int ks = 0; ks < 2; ks++) {
            uint32_t coffA = (uint32_t)(ks * 32 + ak8 * 16);
            uint32_t coffB = (uint32_t)(ks * 32 + bk8 * 16);
            uint32_t bh[8], bl[8];
#pragma unroll
            for (int nx = 0; nx < 2; nx++) {
                uint32_t off = boffbase + (uint32_t)(nx * 1024) + (coffB ^ bxor);
                LDSM4(&bh[nx * 4], Bh + off);
                LDSM4(&bl[nx * 4], Bl + off);
            }
#pragma unroll
            for (int mi = 0; mi < 4; mi++) {
                uint32_t offa = aoffbase + (uint32_t)(mi * 1024) + (coffA ^ axor);
                uint32_t ah[4], al[4];
                LDSM4(ah, Ah + offa);
                LDSM4(al, Al + offa);
#pragma unroll
                for (int ni = 0; ni < 4; ni++) {
                    MMA16816(acc[mi][ni], ah, &bh[ni * 2]);
                    MMA16816(acc[mi][ni], ah, &bl[ni * 2]);
                    MMA16816(acc[mi][ni], al, &bh[ni * 2]);
                }
            }
        }
        if (c + 2 < 32) GEMM_ISSUE(c + 2);
    }
    CP_WAIT(0);

    const int mode = jb.mode;
    const float scale = jb.scale;
#pragma unroll
    for (int mi = 0; mi < 4; mi++) {
        int r0 = m0 + wm * 64 + mi * 16 + (l >> 2);
#pragma unroll
        for (int ni = 0; ni < 4; ni++) {
            int col = n0 + wn * 32 + ni * 8 + (l & 3) * 2;
            float2 bv = *(const float2*)&jb.bias[col];
            float v00 = acc[mi][ni][0] + bv.x, v01 = acc[mi][ni][1] + bv.y;
            float v10 = acc[mi][ni][2] + bv.x, v11 = acc[mi][ni][3] + bv.y;
            v00 *= scale; v01 *= scale; v10 *= scale; v11 *= scale;
            int hh = col >> 6, d = col & 63;
#pragma unroll
            for (int rr = 0; rr < 2; rr++) {
                int r = r0 + rr * 8;
                float a0 = rr ? v10 : v00, a1 = rr ? v11 : v01;
                int bb = r >> 11, s = r & 2047;
                if (mode == 1) {
                    uint32_t ph = pack_bf16x2(a0, a1);
                    float e0 = a0 - __uint_as_float(ph << 16);
                    float e1 = a1 - __uint_as_float(ph & 0xFFFF0000u);
                    uint32_t pl = pack_bf16x2(e0, e1);
                    size_t a = ((size_t)(bb * H_ + hh) * S_ + s) * 64 + d;
                    *(uint32_t*)(jb.oh + a) = ph;
                    *(uint32_t*)(jb.ol + a) = pl;
                } else {
                    // mode 2: single fp16, transposed [B,H,64,S]
                    size_t a = ((size_t)(bb * H_ + hh) * 64 + d) * (size_t)S_ + s;
                    __half* vp = (__half*)jb.oh;
                    vp[a]      = __float2half(a0);
                    vp[a + S_] = __float2half(a1);
                }
            }
        }
    }
}

// ---------------------------------------------------------------------------
// fp16 single-term GEMM for the O projection: out = X*W^T + bias (fp32 out)
// ---------------------------------------------------------------------------
#define GO_STAGE 16384
#define GO_SMEM (3 * GO_STAGE)

__global__ __launch_bounds__(256) void gemm_o(
    const __half* __restrict__ X, const __half* __restrict__ W,
    const float* __restrict__ bias, float* __restrict__ out)
{
    extern __shared__ char sb[];
    const int t = threadIdx.x, l = t & 31, wid = t >> 5;
    const int m0 = blockIdx.y * 128, n0 = blockIdx.x * 128;
    const int wm = wid >> 2, wn = wid & 3;

    const int arow = l & 15;
    const int ak8  = (l >> 4) & 1;
    const uint32_t axor = (uint32_t)((arow & 6) << 3);
    const int brow = (l & 7) + ((l >> 4) & 1) * 8;
    const int bk8  = (l >> 3) & 1;
    const uint32_t bxor = (uint32_t)((brow & 6) << 3);

    const uint32_t sbase = smem_u32(sb);

    float acc[4][4][4];
#pragma unroll
    for (int a = 0; a < 4; a++)
#pragma unroll
        for (int b = 0; b < 4; b++)
#pragma unroll
            for (int c = 0; c < 4; c++) acc[a][b][c] = 0.f;

#define GO_ISSUE(cc) do {                                                     \
    int _c = (cc);                                                            \
    uint32_t st = sbase + (uint32_t)((_c % 3) * GO_STAGE);                    \
    int kc = _c * 32;                                                         \
    _Pragma("unroll")                                                         \
    for (int j = 0; j < 4; j++) {                                             \
        int idx = j * 256 + t;                                                \
        int half = idx >> 9;                                                  \
        int e = idx & 511;                                                    \
        int row = e >> 2;                                                     \
        uint32_t coff = (uint32_t)((e & 3) * 16);                             \
        uint32_t dst = st + (uint32_t)(half * 8192 + row * 64) +              \
                       (coff ^ ((uint32_t)(row & 6) << 3));                   \
        const __half* src = half == 0                                         \
            ? X + (size_t)(m0 + row) * D_ + kc + (e & 3) * 8                  \
            : W + (size_t)(n0 + row) * D_ + kc + (e & 3) * 8;                 \
        CP_ASYNC16(dst, src);                                                 \
    }                                                                         \
    CP_COMMIT();                                                              \
} while (0)

    GO_ISSUE(0);
    GO_ISSUE(1);

    const uint32_t aoffbase = (uint32_t)((wm * 64 + arow) * 64);
    const uint32_t boffbase = (uint32_t)((wn * 32 + brow) * 64);

    for (int c = 0; c < 32; c++) {
        CP_WAIT(1);
        __syncthreads();
        uint32_t As = sbase + (uint32_t)((c % 3) * GO_STAGE);
        uint32_t Ws = As + 8192;

#pragma unroll
        for (int ks = 0; ks < 2; ks++) {
            uint32_t coffA = (uint32_t)(ks * 32 + ak8 * 16);
            uint32_t coffB = (uint32_t)(ks * 32 + bk8 * 16);
            uint32_t bh[8];
#pragma unroll
            for (int nx = 0; nx < 2; nx++) {
                uint32_t off = boffbase + (uint32_t)(nx * 1024) + (coffB ^ bxor);
                LDSM4(&bh[nx * 4], Ws + off);
            }
#pragma unroll
            for (int mi = 0; mi < 4; mi++) {
                uint32_t offa = aoffbase + (uint32_t)(mi * 1024) + (coffA ^ axor);
                uint32_t ah[4];
                LDSM4(ah, As + offa);
#pragma unroll
                for (int ni = 0; ni < 4; ni++)
                    MMA16816H(acc[mi][ni], ah, &bh[ni * 2]);
            }
        }
        if (c + 2 < 32) GO_ISSUE(c + 2);
    }
    CP_WAIT(0);

#pragma unroll
    for (int mi = 0; mi < 4; mi++) {
        int r0 = m0 + wm * 64 + mi * 16 + (l >> 2);
#pragma unroll
        for (int ni = 0; ni < 4; ni++) {
            int col = n0 + wn * 32 + ni * 8 + (l & 3) * 2;
            float2 bv = *(const float2*)&bias[col];
            *(float2*)&out[(size_t)r0 * D_ + col] =
                make_float2(acc[mi][ni][0] + bv.x, acc[mi][ni][1] + bv.y);
            *(float2*)&out[(size_t)(r0 + 8) * D_ + col] =
                make_float2(acc[mi][ni][2] + bv.x, acc[mi][ni][3] + bv.y);
        }
    }
}

// ---------------------------------------------------------------------------
// HMMA flash attention, 128 threads / 64 q-rows per CTA, 3 CTAs/SM.
// QK^T: bf16 3-term split. PV: single fp16 (P fp16, V fp16).
// Stage = Kh(8K)|Kl(8K)|V16(8K) = 24KB, double buffered. Q staged via buf 0.
// O written single fp16 to [M, D].
// ---------------------------------------------------------------------------
#define FSTAGE 24576
#define FLASH_SMEM (2 * FSTAGE)

__global__ __launch_bounds__(128, 3) void flash_mma(
    const __nv_bfloat16* __restrict__ Qh, const __nv_bfloat16* __restrict__ Ql,
    const __nv_bfloat16* __restrict__ Kh, const __nv_bfloat16* __restrict__ Kl,
    const __half* __restrict__ Vp, __half* __restrict__ Op)
{
    extern __shared__ char sb[];
    const int t = threadIdx.x, l = t & 31, w = t >> 5;       // 4 warps
    const int bh = blockIdx.y, b = bh >> 4, h = bh & 15;
    const int qb = (int)(gridDim.x - 1 - blockIdx.x) * 64;   // heavy CTAs first

    const uint32_t sbase = smem_u32(sb);
    const size_t base = (size_t)bh * S_ * 64;

    const int arow = l & 15;
    const int ak8  = (l >> 4) & 1;
    const int brow = (l & 7) + ((l >> 4) & 1) * 8;
    const int bk8  = (l >> 3) & 1;

    // ---- stage Q (64x64 hi+lo = 16KB) through stage buffer 0 ----
#pragma unroll
    for (int it = 0; it < 8; it++) {
        int idx = it * 128 + t;
        int mat = idx >> 9;              // 0 Qh, 1 Ql
        int r   = (idx >> 3) & 63;
        int c   = idx & 7;
        const __nv_bfloat16* src = (mat ? Ql : Qh) + base + (size_t)(qb + r) * 64 + c * 8;
        uint32_t dst = sbase + (uint32_t)(mat * 8192 + r * 128 + ((c ^ (r & 7)) * 16));
        CP_ASYNC16(dst, src);
    }
    CP_COMMIT();
    CP_WAIT(0);
    __syncthreads();

    // ---- Q fragments to registers ----
    uint32_t qhA[4][4], qlA[4][4];
    {
        int qrow = w * 16 + arow;
        uint32_t rbase = sbase + (uint32_t)(qrow * 128);
#pragma unroll
        for (int kc = 0; kc < 4; kc++) {
            uint32_t off = (uint32_t)(((kc * 2 + ak8) ^ (qrow & 7)) * 16);
            LDSM4(qhA[kc], rbase + off);
            LDSM4(qlA[kc], rbase + 8192 + off);
        }
    }
    __syncthreads();

#define FLASH_ISSUE(kt_) do {                                                 \
    int _key0 = (kt_) * 64;                                                   \
    uint32_t _st = sbase + (uint32_t)(((kt_) & 1) * FSTAGE);                  \
    _Pragma("unroll")                                                         \
    for (int it = 0; it < 12; it++) {                                         \
        int idx = it * 128 + t;                                               \
        int mat = idx >> 9;                                                   \
        int r   = (idx >> 3) & 63;                                            \
        int c   = idx & 7;                                                    \
        const void* src;                                                      \
        if      (mat == 0) src = Kh + base + (size_t)(_key0 + r) * 64 + c * 8;\
        else if (mat == 1) src = Kl + base + (size_t)(_key0 + r) * 64 + c * 8;\
        else               src = Vp + base + (size_t)r * S_ + _key0 + c * 8;  \
        uint32_t dst = _st + (uint32_t)(mat * 8192 + r * 128 + ((c ^ (r & 7)) * 16)); \
        CP_ASYNC16(dst, src);                                                 \
    }                                                                         \
    CP_COMMIT();                                                              \
} while (0)

    FLASH_ISSUE(0);

    float O[8][4];
#pragma unroll
    for (int d = 0; d < 8; d++)
#pragma unroll
        for (int c = 0; c < 4; c++) O[d][c] = 0.f;
    float m0 = -1e30f, m1 = -1e30f, l0 = 0.f, l1 = 0.f;

    const int wmin = qb + w * 16;
    const int r0l  = wmin + (l >> 2);
    const int nt   = qb / 64 + 1;

    for (int kt = 0; kt < nt; kt++) {
        CP_WAIT(0);
        __syncthreads();
        if (kt + 1 < nt) FLASH_ISSUE(kt + 1);

        const int key0 = kt * 64;
        uint32_t st = sbase + (uint32_t)((kt & 1) * FSTAGE);

        // ---- S = Q K^T (3-term bf16 split) ----
        float S[8][4];
#pragma unroll
        for (int nf = 0; nf < 8; nf++)
#pragma unroll
            for (int c = 0; c < 4; c++) S[nf][c] = 0.f;

#pragma unroll
        for (int kc = 0; kc < 4; kc++) {
            uint32_t kbh[16], kbl[16];
#pragma unroll
            for (int g = 0; g < 4; g++) {
                int row = g * 16 + brow;
                uint32_t off = (uint32_t)(row * 128 + (((kc * 2 + bk8) ^ (row & 7)) * 16));
                LDSM4(&kbh[g * 4], st + off);
                LDSM4(&kbl[g * 4], st + 8192 + off);
            }
#pragma unroll
            for (int nf = 0; nf < 8; nf++) {
                int ix = (nf >> 1) * 4 + (nf & 1) * 2;
                MMA16816(S[nf], qhA[kc], &kbh[ix]);
                MMA16816(S[nf], qhA[kc], &kbl[ix]);
                MMA16816(S[nf], qlA[kc], &kbh[ix]);
            }
        }

        // ---- causal mask (diagonal tile only) ----
        if (key0 + 63 > wmin) {
#pragma unroll
            for (int nf = 0; nf < 8; nf++) {
                int k0 = key0 + nf * 8 + (l & 3) * 2;
                if (k0     > r0l)     S[nf][0] = -1e30f;
                if (k0 + 1 > r0l)     S[nf][1] = -1e30f;
                if (k0     > r0l + 8) S[nf][2] = -1e30f;
                if (k0 + 1 > r0l + 8) S[nf][3] = -1e30f;
            }
        }

        // ---- online softmax ----
        float mx0 = -1e30f, mx1 = -1e30f;
#pragma unroll
        for (int nf = 0; nf < 8; nf++) {
            mx0 = fmaxf(mx0, fmaxf(S[nf][0], S[nf][1]));
            mx1 = fmaxf(mx1, fmaxf(S[nf][2], S[nf][3]));
        }
        mx0 = fmaxf(mx0, __shfl_xor_sync(0xFFFFFFFF, mx0, 1));
        mx0 = fmaxf(mx0, __shfl_xor_sync(0xFFFFFFFF, mx0, 2));
        mx1 = fmaxf(mx1, __shfl_xor_sync(0xFFFFFFFF, mx1, 1));
        mx1 = fmaxf(mx1, __shfl_xor_sync(0xFFFFFFFF, mx1, 2));

        float mn0 = fmaxf(m0, mx0), mn1 = fmaxf(m1, mx1);
        float al0 = __expf(m0 - mn0), al1 = __expf(m1 - mn1);
        m0 = mn0; m1 = mn1;

        uint32_t pha[4][4];
        float rs0 = 0.f, rs1 = 0.f;
#pragma unroll
        for (int nf = 0; nf < 8; nf++) {
            float p00 = __expf(S[nf][0] - mn0);
            float p01 = __expf(S[nf][1] - mn0);
            float p10 = __expf(S[nf][2] - mn1);
            float p11 = __expf(S[nf][3] - mn1);
            rs0 += p00 + p01; rs1 += p10 + p11;
            int kc = nf >> 1, a0 = (nf & 1) * 2;
            pha[kc][a0]     = pack_f16x2(p00, p01);
            pha[kc][a0 + 1] = pack_f16x2(p10, p11);
        }
        rs0 += __shfl_xor_sync(0xFFFFFFFF, rs0, 1);
        rs0 += __shfl_xor_sync(0xFFFFFFFF, rs0, 2);
        rs1 += __shfl_xor_sync(0xFFFFFFFF, rs1, 1);
        rs1 += __shfl_xor_sync(0xFFFFFFFF, rs1, 2);
        l0 = l0 * al0 + rs0;
        l1 = l1 * al1 + rs1;

#pragma unroll
        for (int d = 0; d < 8; d++) {
            O[d][0] *= al0; O[d][1] *= al0;
            O[d][2] *= al1; O[d][3] *= al1;
        }

        // ---- O += P V (single fp16) ----
#pragma unroll
        for (int kc = 0; kc < 4; kc++) {
            uint32_t vb[16];
#pragma unroll
            for (int g = 0; g < 4; g++) {
                int row = g * 16 + brow;
                uint32_t off = (uint32_t)(row * 128 + (((kc * 2 + bk8) ^ (row & 7)) * 16));
                LDSM4(&vb[g * 4], st + 16384 + off);
            }
#pragma unroll
            for (int df = 0; df < 8; df++) {
                int ix = (df >> 1) * 4 + (df & 1) * 2;
                MMA16816H(O[df], pha[kc], &vb[ix]);
            }
        }
    }

    // ---- write O single fp16 to [M, D] layout ----
    const float inv0 = 1.f / l0, inv1 = 1.f / l1;
    const int r0g = qb + w * 16 + (l >> 2);
#pragma unroll
    for (int df = 0; df < 8; df++) {
        int d = df * 8 + (l & 3) * 2;
        size_t a0 = ((size_t)(b * S_ + r0g)) * D_ + h * 64 + d;
        size_t a1 = ((size_t)(b * S_ + r0g + 8)) * D_ + h * 64 + d;
        *(uint32_t*)(Op + a0) = pack_f16x2(O[df][0] * inv0, O[df][1] * inv0);
        *(uint32_t*)(Op + a1) = pack_f16x2(O[df][2] * inv1, O[df][3] * inv1);
    }
}

// ---------------------------------------------------------------------------
extern "C" void kernel_launch(void* const* d_in, const int* in_sizes, int n_in,
                              void* d_out, int out_size)
{
    const float* query = (const float*)d_in[0];
    const float* key   = (const float*)d_in[1];
    const float* value = (const float*)d_in[2];
    const float* Wq    = (const float*)d_in[3];
    const float* bq    = (const float*)d_in[4];
    const float* Wk    = (const float*)d_in[5];
    const float* bk    = (const float*)d_in[6];
    const float* Wv    = (const float*)d_in[7];
    const float* bv    = (const float*)d_in[8];
    const float* Wo    = (const float*)d_in[9];
    const float* bo    = (const float*)d_in[10];
    float* out = (float*)d_out;

    __nv_bfloat16 *pQh, *pQl, *pKh, *pKl;
    __half *pV16, *pwO16;
    __nv_bfloat16 *paQh, *paQl, *paKh, *paKl, *paVh, *paVl;
    __nv_bfloat16 *pwQh, *pwQl, *pwKh, *pwKl, *pwVh, *pwVl;
    cudaGetSymbolAddress((void**)&pQh, g_Qh);
    cudaGetSymbolAddress((void**)&pQl, g_Ql);
    cudaGetSymbolAddress((void**)&pKh, g_Kh);
    cudaGetSymbolAddress((void**)&pKl, g_Kl);
    cudaGetSymbolAddress((void**)&pV16, g_V16);
    cudaGetSymbolAddress((void**)&paQh, g_aQh);
    cudaGetSymbolAddress((void**)&paQl, g_aQl);
    cudaGetSymbolAddress((void**)&paKh, g_aKh);
    cudaGetSymbolAddress((void**)&paKl, g_aKl);
    cudaGetSymbolAddress((void**)&paVh, g_aVh);
    cudaGetSymbolAddress((void**)&paVl, g_aVl);
    cudaGetSymbolAddress((void**)&pwQh, g_wQh);
    cudaGetSymbolAddress((void**)&pwQl, g_wQl);
    cudaGetSymbolAddress((void**)&pwKh, g_wKh);
    cudaGetSymbolAddress((void**)&pwKl, g_wKl);
    cudaGetSymbolAddress((void**)&pwVh, g_wVh);
    cudaGetSymbolAddress((void**)&pwVl, g_wVl);
    cudaGetSymbolAddress((void**)&pwO16, g_wO16);

    cudaFuncSetAttribute(gemm_mma, cudaFuncAttributeMaxDynamicSharedMemorySize,
                         GEMM_SMEM);
    cudaFuncSetAttribute(gemm_o, cudaFuncAttributeMaxDynamicSharedMemorySize,
                         GO_SMEM);
    cudaFuncSetAttribute(flash_mma, cudaFuncAttributeMaxDynamicSharedMemorySize,
                         FLASH_SMEM);

    const int nA4 = M_ * D_ / 4;
    const int nW4 = D_ * D_ / 4;

    // 1) all splits in one launch (Wo -> single fp16)
    SJobs sj;
    sj.src[0] = query; sj.hi[0] = paQh; sj.lo[0] = paQl; sj.n4[0] = nA4; sj.f16[0] = 0;
    sj.src[1] = key;   sj.hi[1] = paKh; sj.lo[1] = paKl; sj.n4[1] = nA4; sj.f16[1] = 0;
    sj.src[2] = value; sj.hi[2] = paVh; sj.lo[2] = paVl; sj.n4[2] = nA4; sj.f16[2] = 0;
    sj.src[3] = Wq;    sj.hi[3] = pwQh; sj.lo[3] = pwQl; sj.n4[3] = nW4; sj.f16[3] = 0;
    sj.src[4] = Wk;    sj.hi[4] = pwKh; sj.lo[4] = pwKl; sj.n4[4] = nW4; sj.f16[4] = 0;
    sj.src[5] = Wv;    sj.hi[5] = pwVh; sj.lo[5] = pwVl; sj.n4[5] = nW4; sj.f16[5] = 0;
    sj.src[6] = Wo;    sj.hi[6] = pwO16; sj.lo[6] = pwO16; sj.n4[6] = nW4; sj.f16[6] = 1;
    split_all<<<dim3(1024, 7), 256>>>(sj);

    // 2) fused Q/K/V projection GEMMs (bf16 3-term)
    GJobs gq;
    gq.j[0] = GJob{paQh, paQl, pwQh, pwQl, bq, pQh, pQl, 1, 0.125f};
    gq.j[1] = GJob{paKh, paKl, pwKh, pwKl, bk, pKh, pKl, 1, 1.0f};
    gq.j[2] = GJob{paVh, paVl, pwVh, pwVl, bv, (__nv_bfloat16*)pV16, nullptr, 2, 1.0f};
    gemm_mma<<<dim3(D_ / 128, M_ / 128, 3), 256, GEMM_SMEM>>>(gq);

    // 3) attention -> single fp16 O into paQh (reused as __half buffer)
    flash_mma<<<dim3(S_ / 64, B_ * H_), 128, FLASH_SMEM>>>(
        pQh, pQl, pKh, pKl, pV16, (__half*)paQh);

    // 4) O projection (fp16 single-term) -> fp32 out
    gemm_o<<<dim3(D_ / 128, M_ / 128), 256, GO_SMEM>>>(
        (const __half*)paQh, pwO16, bo, out);
}

// round 15
// speedup vs baseline: 8.4133x; 1.7497x over previous
#include <cuda_runtime.h>
#include <cuda_fp16.h>
#include <cstdint>
#include <math.h>

#define B_  2
#define S_  2048
#define D_  1024
#define H_  16
#define DK_ 64
#define M_  (B_ * S_)

// Scratch (allocation-free rule: __device__ globals) — all fp16 now
__device__ __half g_Q16[M_ * D_];   // [B,H,S,64], scale folded
__device__ __half g_K16[M_ * D_];   // [B,H,S,64]
__device__ __half g_V16[M_ * D_];   // transposed [B,H,64,S]
__device__ __half g_aQ16[M_ * D_];  // query activation; reused as flash O
__device__ __half g_aK16[M_ * D_];
__device__ __half g_aV16[M_ * D_];
__device__ __half g_wQ16[D_ * D_];
__device__ __half g_wK16[D_ * D_];
__device__ __half g_wV16[D_ * D_];
__device__ __half g_wO16[D_ * D_];

// ---------------------------------------------------------------------------
__device__ __forceinline__ uint32_t smem_u32(const void* p) {
    return (uint32_t)__cvta_generic_to_shared(p);
}

#define CP_ASYNC16(dst_u32, src_ptr) \
    asm volatile("cp.async.cg.shared.global [%0], [%1], 16;" :: "r"(dst_u32), "l"(src_ptr))
#define CP_COMMIT() asm volatile("cp.async.commit_group;")
#define CP_WAIT(n)  asm volatile("cp.async.wait_group %0;" :: "n"(n) : "memory")

#define LDSM4(r, addr) asm volatile( \
    "ldmatrix.sync.aligned.m8n8.x4.shared.b16 {%0,%1,%2,%3}, [%4];" \
    : "=r"((r)[0]), "=r"((r)[1]), "=r"((r)[2]), "=r"((r)[3]) : "r"(addr))

#define MMA16816H(d, a, b) asm volatile( \
    "mma.sync.aligned.m16n8k16.row.col.f32.f16.f16.f32 " \
    "{%0,%1,%2,%3}, {%4,%5,%6,%7}, {%8,%9}, {%0,%1,%2,%3};" \
    : "+f"((d)[0]), "+f"((d)[1]), "+f"((d)[2]), "+f"((d)[3]) \
    : "r"((a)[0]), "r"((a)[1]), "r"((a)[2]), "r"((a)[3]), \
      "r"((b)[0]), "r"((b)[1]))

__device__ __forceinline__ uint32_t pack_f16x2(float lo, float hi) {
    uint32_t r;
    asm("cvt.rn.f16x2.f32 %0, %1, %2;" : "=r"(r) : "f"(hi), "f"(lo));
    return r;
}

// ---------------------------------------------------------------------------
// fused fp32 -> fp16 conversion for all 7 tensors
// ---------------------------------------------------------------------------
struct SJobs {
    const float* src[7];
    __half* dst[7];
    int n4[7];
};

__global__ __launch_bounds__(256) void split_all(SJobs s)
{
    const int z = blockIdx.y;
    const int n4 = s.n4[z];
    const float* __restrict__ x = s.src[z];
    uint2* __restrict__ d = (uint2*)s.dst[z];

    int i0 = blockIdx.x * 1024 + threadIdx.x;
    if (i0 >= n4) return;
#pragma unroll
    for (int j = 0; j < 4; j++) {
        int i = i0 + j * 256;
        if (i < n4) {
            float4 v = ((const float4*)x)[i];
            d[i] = make_uint2(pack_f16x2(v.x, v.y), pack_f16x2(v.z, v.w));
        }
    }
}

// ---------------------------------------------------------------------------
// fp16 1-term GEMM, multi-job: acc[m,n] = sum_k X[m,k]*W[n,k]
// mode 0: fp32 out = acc + bias                       (O projection)
// mode 1: fp16 out to [B,H,S,64], val = (acc+bias)*scale   (Q, K)
// mode 2: fp16 out to [B,H,64,S] transposed, val = acc+bias (V)
// Block 128x128, 8 warps, k-chunk 32, 3 stages x 16KB.
// ---------------------------------------------------------------------------
#define GSTAGE 16384
#define GEMM_SMEM (3 * GSTAGE)

struct GJob {
    const __half *X, *W;
    const float* bias;
    float* outf;
    __half* oh;
    int mode;
    float scale;
};
struct GJobs { GJob j[3]; };

__global__ __launch_bounds__(256) void gemm_h(GJobs jobs)
{
    extern __shared__ char sb[];
    const GJob jb = jobs.j[blockIdx.z];
    const __half* __restrict__ X = jb.X;
    const __half* __restrict__ W = jb.W;

    const int t = threadIdx.x, l = t & 31, wid = t >> 5;
    const int m0 = blockIdx.y * 128, n0 = blockIdx.x * 128;
    const int wm = wid >> 2, wn = wid & 3;

    const int arow = l & 15;
    const int ak8  = (l >> 4) & 1;
    const uint32_t axor = (uint32_t)((arow & 6) << 3);
    const int brow = (l & 7) + ((l >> 4) & 1) * 8;
    const int bk8  = (l >> 3) & 1;
    const uint32_t bxor = (uint32_t)((brow & 6) << 3);

    const uint32_t sbase = smem_u32(sb);

    float acc[4][4][4];
#pragma unroll
    for (int a = 0; a < 4; a++)
#pragma unroll
        for (int b = 0; b < 4; b++)
#pragma unroll
            for (int c = 0; c < 4; c++) acc[a][b][c] = 0.f;

#define GH_ISSUE(cc) do {                                                     \
    int _c = (cc);                                                            \
    uint32_t st = sbase + (uint32_t)((_c % 3) * GSTAGE);                      \
    int kc = _c * 32;                                                         \
    _Pragma("unroll")                                                         \
    for (int j = 0; j < 4; j++) {                                             \
        int idx = j * 256 + t;                                                \
        int half = idx >> 9;                                                  \
        int e = idx & 511;                                                    \
        int row = e >> 2;                                                     \
        uint32_t coff = (uint32_t)((e & 3) * 16);                             \
        uint32_t dst = st + (uint32_t)(half * 8192 + row * 64) +              \
                       (coff ^ ((uint32_t)(row & 6) << 3));                   \
        const __half* src = half == 0                                         \
            ? X + (size_t)(m0 + row) * D_ + kc + (e & 3) * 8                  \
            : W + (size_t)(n0 + row) * D_ + kc + (e & 3) * 8;                 \
        CP_ASYNC16(dst, src);                                                 \
    }                                                                         \
    CP_COMMIT();                                                              \
} while (0)

    GH_ISSUE(0);
    GH_ISSUE(1);

    const uint32_t aoffbase = (uint32_t)((wm * 64 + arow) * 64);
    const uint32_t boffbase = (uint32_t)((wn * 32 + brow) * 64);

    for (int c = 0; c < 32; c++) {
        CP_WAIT(1);
        __syncthreads();
        uint32_t As = sbase + (uint32_t)((c % 3) * GSTAGE);
        uint32_t Ws = As + 8192;

#pragma unroll
        for (int ks = 0; ks < 2; ks++) {
            uint32_t coffA = (uint32_t)(ks * 32 + ak8 * 16);
            uint32_t coffB = (uint32_t)(ks * 32 + bk8 * 16);
            uint32_t bh[8];
#pragma unroll
            for (int nx = 0; nx < 2; nx++) {
                uint32_t off = boffbase + (uint32_t)(nx * 1024) + (coffB ^ bxor);
                LDSM4(&bh[nx * 4], Ws + off);
            }
#pragma unroll
            for (int mi = 0; mi < 4; mi++) {
                uint32_t offa = aoffbase + (uint32_t)(mi * 1024) + (coffA ^ axor);
                uint32_t ah[4];
                LDSM4(ah, As + offa);
#pragma unroll
                for (int ni = 0; ni < 4; ni++)
                    MMA16816H(acc[mi][ni], ah, &bh[ni * 2]);
            }
        }
        if (c + 2 < 32) GH_ISSUE(c + 2);
    }
    CP_WAIT(0);

    const int mode = jb.mode;
    const float scale = jb.scale;
#pragma unroll
    for (int mi = 0; mi < 4; mi++) {
        int r0 = m0 + wm * 64 + mi * 16 + (l >> 2);
#pragma unroll
        for (int ni = 0; ni < 4; ni++) {
            int col = n0 + wn * 32 + ni * 8 + (l & 3) * 2;
            float2 bv = *(const float2*)&jb.bias[col];
            float v00 = acc[mi][ni][0] + bv.x, v01 = acc[mi][ni][1] + bv.y;
            float v10 = acc[mi][ni][2] + bv.x, v11 = acc[mi][ni][3] + bv.y;
            if (mode == 0) {
                *(float2*)&jb.outf[(size_t)r0 * D_ + col] = make_float2(v00, v01);
                *(float2*)&jb.outf[(size_t)(r0 + 8) * D_ + col] = make_float2(v10, v11);
            } else {
                v00 *= scale; v01 *= scale; v10 *= scale; v11 *= scale;
                int hh = col >> 6, d = col & 63;
#pragma unroll
                for (int rr = 0; rr < 2; rr++) {
                    int r = r0 + rr * 8;
                    float a0 = rr ? v10 : v00, a1 = rr ? v11 : v01;
                    int bb = r >> 11, s = r & 2047;
                    if (mode == 1) {
                        size_t a = ((size_t)(bb * H_ + hh) * S_ + s) * 64 + d;
                        *(uint32_t*)(jb.oh + a) = pack_f16x2(a0, a1);
                    } else {
                        size_t a = ((size_t)(bb * H_ + hh) * 64 + d) * (size_t)S_ + s;
                        jb.oh[a]      = __float2half(a0);
                        jb.oh[a + S_] = __float2half(a1);
                    }
                }
            }
        }
    }
}

// ---------------------------------------------------------------------------
// fp16 flash attention, 128 threads / 64 q-rows per CTA, 3 CTAs/SM.
// QK^T and PV both single-term fp16, fp32 accumulators + fp32 softmax.
// Stage = K(8KB)|V(8KB) = 16KB, double buffered. Q staged through buf 0.
// ---------------------------------------------------------------------------
#define FSTAGE 16384
#define FLASH_SMEM (2 * FSTAGE)

__global__ __launch_bounds__(128, 3) void flash_mma(
    const __half* __restrict__ Qp, const __half* __restrict__ Kp,
    const __half* __restrict__ Vp, __half* __restrict__ Op)
{
    extern __shared__ char sb[];
    const int t = threadIdx.x, l = t & 31, w = t >> 5;       // 4 warps
    const int bh = blockIdx.y, b = bh >> 4, h = bh & 15;
    const int qb = (int)(gridDim.x - 1 - blockIdx.x) * 64;   // heavy CTAs first

    const uint32_t sbase = smem_u32(sb);
    const size_t base = (size_t)bh * S_ * 64;

    const int arow = l & 15;
    const int ak8  = (l >> 4) & 1;
    const int brow = (l & 7) + ((l >> 4) & 1) * 8;
    const int bk8  = (l >> 3) & 1;

    // ---- stage Q (64x64 fp16 = 8KB) through stage buffer 0 ----
#pragma unroll
    for (int it = 0; it < 4; it++) {
        int idx = it * 128 + t;          // 512 16B-copies
        int r   = (idx >> 3) & 63;
        int c   = idx & 7;
        const __half* src = Qp + base + (size_t)(qb + r) * 64 + c * 8;
        uint32_t dst = sbase + (uint32_t)(r * 128 + ((c ^ (r & 7)) * 16));
        CP_ASYNC16(dst, src);
    }
    CP_COMMIT();
    CP_WAIT(0);
    __syncthreads();

    // ---- Q fragments to registers ----
    uint32_t qA[4][4];
    {
        int qrow = w * 16 + arow;
        uint32_t rbase = sbase + (uint32_t)(qrow * 128);
#pragma unroll
        for (int kc = 0; kc < 4; kc++) {
            uint32_t off = (uint32_t)(((kc * 2 + ak8) ^ (qrow & 7)) * 16);
            LDSM4(qA[kc], rbase + off);
        }
    }
    __syncthreads();    // all warps done with Q before stage 0 reuse

#define FLASH_ISSUE(kt_) do {                                                 \
    int _key0 = (kt_) * 64;                                                   \
    uint32_t _st = sbase + (uint32_t)(((kt_) & 1) * FSTAGE);                  \
    _Pragma("unroll")                                                         \
    for (int it = 0; it < 8; it++) {                                          \
        int idx = it * 128 + t;                                               \
        int mat = idx >> 9;                                                   \
        int r   = (idx >> 3) & 63;                                            \
        int c   = idx & 7;                                                    \
        const __half* src = mat == 0                                          \
            ? Kp + base + (size_t)(_key0 + r) * 64 + c * 8                    \
            : Vp + base + (size_t)r * S_ + _key0 + c * 8;                     \
        uint32_t dst = _st + (uint32_t)(mat * 8192 + r * 128 + ((c ^ (r & 7)) * 16)); \
        CP_ASYNC16(dst, src);                                                 \
    }                                                                         \
    CP_COMMIT();                                                              \
} while (0)

    FLASH_ISSUE(0);

    float O[8][4];
#pragma unroll
    for (int d = 0; d < 8; d++)
#pragma unroll
        for (int c = 0; c < 4; c++) O[d][c] = 0.f;
    float m0 = -1e30f, m1 = -1e30f, l0 = 0.f, l1 = 0.f;

    const int wmin = qb + w * 16;
    const int r0l  = wmin + (l >> 2);
    const int nt   = qb / 64 + 1;

    for (int kt = 0; kt < nt; kt++) {
        CP_WAIT(0);
        __syncthreads();
        if (kt + 1 < nt) FLASH_ISSUE(kt + 1);

        const int key0 = kt * 64;
        uint32_t st = sbase + (uint32_t)((kt & 1) * FSTAGE);

        // ---- S = Q K^T (fp16 single-term) ----
        float S[8][4];
#pragma unroll
        for (int nf = 0; nf < 8; nf++)
#pragma unroll
            for (int c = 0; c < 4; c++) S[nf][c] = 0.f;

#pragma unroll
        for (int kc = 0; kc < 4; kc++) {
            uint32_t kb[16];
#pragma unroll
            for (int g = 0; g < 4; g++) {
                int row = g * 16 + brow;
                uint32_t off = (uint32_t)(row * 128 + (((kc * 2 + bk8) ^ (row & 7)) * 16));
                LDSM4(&kb[g * 4], st + off);
            }
#pragma unroll
            for (int nf = 0; nf < 8; nf++) {
                int ix = (nf >> 1) * 4 + (nf & 1) * 2;
                MMA16816H(S[nf], qA[kc], &kb[ix]);
            }
        }

        // ---- causal mask (diagonal tile only) ----
        if (key0 + 63 > wmin) {
#pragma unroll
            for (int nf = 0; nf < 8; nf++) {
                int k0 = key0 + nf * 8 + (l & 3) * 2;
                if (k0     > r0l)     S[nf][0] = -1e30f;
                if (k0 + 1 > r0l)     S[nf][1] = -1e30f;
                if (k0     > r0l + 8) S[nf][2] = -1e30f;
                if (k0 + 1 > r0l + 8) S[nf][3] = -1e30f;
            }
        }

        // ---- online softmax ----
        float mx0 = -1e30f, mx1 = -1e30f;
#pragma unroll
        for (int nf = 0; nf < 8; nf++) {
            mx0 = fmaxf(mx0, fmaxf(S[nf][0], S[nf][1]));
            mx1 = fmaxf(mx1, fmaxf(S[nf][2], S[nf][3]));
        }
        mx0 = fmaxf(mx0, __shfl_xor_sync(0xFFFFFFFF, mx0, 1));
        mx0 = fmaxf(mx0, __shfl_xor_sync(0xFFFFFFFF, mx0, 2));
        mx1 = fmaxf(mx1, __shfl_xor_sync(0xFFFFFFFF, mx1, 1));
        mx1 = fmaxf(mx1, __shfl_xor_sync(0xFFFFFFFF, mx1, 2));

        float mn0 = fmaxf(m0, mx0), mn1 = fmaxf(m1, mx1);
        float al0 = __expf(m0 - mn0), al1 = __expf(m1 - mn1);
        m0 = mn0; m1 = mn1;

        uint32_t pha[4][4];
        float rs0 = 0.f, rs1 = 0.f;
#pragma unroll
        for (int nf = 0; nf < 8; nf++) {
            float p00 = __expf(S[nf][0] - mn0);
            float p01 = __expf(S[nf][1] - mn0);
            float p10 = __expf(S[nf][2] - mn1);
            float p11 = __expf(S[nf][3] - mn1);
            rs0 += p00 + p01; rs1 += p10 + p11;
            int kc = nf >> 1, a0 = (nf & 1) * 2;
            pha[kc][a0]     = pack_f16x2(p00, p01);
            pha[kc][a0 + 1] = pack_f16x2(p10, p11);
        }
        rs0 += __shfl_xor_sync(0xFFFFFFFF, rs0, 1);
        rs0 += __shfl_xor_sync(0xFFFFFFFF, rs0, 2);
        rs1 += __shfl_xor_sync(0xFFFFFFFF, rs1, 1);
        rs1 += __shfl_xor_sync(0xFFFFFFFF, rs1, 2);
        l0 = l0 * al0 + rs0;
        l1 = l1 * al1 + rs1;

#pragma unroll
        for (int d = 0; d < 8; d++) {
            O[d][0] *= al0; O[d][1] *= al0;
            O[d][2] *= al1; O[d][3] *= al1;
        }

        // ---- O += P V (fp16 single-term) ----
#pragma unroll
        for (int kc = 0; kc < 4; kc++) {
            uint32_t vb[16];
#pragma unroll
            for (int g = 0; g < 4; g++) {
                int row = g * 16 + brow;
                uint32_t off = (uint32_t)(row * 128 + (((kc * 2 + bk8) ^ (row & 7)) * 16));
                LDSM4(&vb[g * 4], st + 8192 + off);
            }
#pragma unroll
            for (int df = 0; df < 8; df++) {
                int ix = (df >> 1) * 4 + (df & 1) * 2;
                MMA16816H(O[df], pha[kc], &vb[ix]);
            }
        }
    }

    // ---- write O fp16 to [M, D] layout ----
    const float inv0 = 1.f / l0, inv1 = 1.f / l1;
    const int r0g = qb + w * 16 + (l >> 2);
#pragma unroll
    for (int df = 0; df < 8; df++) {
        int d = df * 8 + (l & 3) * 2;
        size_t a0 = ((size_t)(b * S_ + r0g)) * D_ + h * 64 + d;
        size_t a1 = ((size_t)(b * S_ + r0g + 8)) * D_ + h * 64 + d;
        *(uint32_t*)(Op + a0) = pack_f16x2(O[df][0] * inv0, O[df][1] * inv0);
        *(uint32_t*)(Op + a1) = pack_f16x2(O[df][2] * inv1, O[df][3] * inv1);
    }
}

// ---------------------------------------------------------------------------
extern "C" void kernel_launch(void* const* d_in, const int* in_sizes, int n_in,
                              void* d_out, int out_size)
{
    const float* query = (const float*)d_in[0];
    const float* key   = (const float*)d_in[1];
    const float* value = (const float*)d_in[2];
    const float* Wq    = (const float*)d_in[3];
    const float* bq    = (const float*)d_in[4];
    const float* Wk    = (const float*)d_in[5];
    const float* bk    = (const float*)d_in[6];
    const float* Wv    = (const float*)d_in[7];
    const float* bv    = (const float*)d_in[8];
    const float* Wo    = (const float*)d_in[9];
    const float* bo    = (const float*)d_in[10];
    float* out = (float*)d_out;

    __half *pQ, *pK, *pV, *paQ, *paK, *paV, *pwQ, *pwK, *pwV, *pwO;
    cudaGetSymbolAddress((void**)&pQ,  g_Q16);
    cudaGetSymbolAddress((void**)&pK,  g_K16);
    cudaGetSymbolAddress((void**)&pV,  g_V16);
    cudaGetSymbolAddress((void**)&paQ, g_aQ16);
    cudaGetSymbolAddress((void**)&paK, g_aK16);
    cudaGetSymbolAddress((void**)&paV, g_aV16);
    cudaGetSymbolAddress((void**)&pwQ, g_wQ16);
    cudaGetSymbolAddress((void**)&pwK, g_wK16);
    cudaGetSymbolAddress((void**)&pwV, g_wV16);
    cudaGetSymbolAddress((void**)&pwO, g_wO16);

    cudaFuncSetAttribute(gemm_h, cudaFuncAttributeMaxDynamicSharedMemorySize,
                         GEMM_SMEM);
    cudaFuncSetAttribute(flash_mma, cudaFuncAttributeMaxDynamicSharedMemorySize,
                         FLASH_SMEM);

    const int nA4 = M_ * D_ / 4;
    const int nW4 = D_ * D_ / 4;

    // 1) all fp32 -> fp16 conversions in one launch
    SJobs sj;
    sj.src[0] = query; sj.dst[0] = paQ; sj.n4[0] = nA4;
    sj.src[1] = key;   sj.dst[1] = paK; sj.n4[1] = nA4;
    sj.src[2] = value; sj.dst[2] = paV; sj.n4[2] = nA4;
    sj.src[3] = Wq;    sj.dst[3] = pwQ; sj.n4[3] = nW4;
    sj.src[4] = Wk;    sj.dst[4] = pwK; sj.n4[4] = nW4;
    sj.src[5] = Wv;    sj.dst[5] = pwV; sj.n4[5] = nW4;
    sj.src[6] = Wo;    sj.dst[6] = pwO; sj.n4[6] = nW4;
    split_all<<<dim3(1024, 7), 256>>>(sj);

    // 2) fused Q/K/V projection GEMMs (fp16 1-term)
    GJobs gq;
    gq.j[0] = GJob{paQ, pwQ, bq, nullptr, pQ, 1, 0.125f};
    gq.j[1] = GJob{paK, pwK, bk, nullptr, pK, 1, 1.0f};
    gq.j[2] = GJob{paV, pwV, bv, nullptr, pV, 2, 1.0f};
    gemm_h<<<dim3(D_ / 128, M_ / 128, 3), 256, GEMM_SMEM>>>(gq);

    // 3) attention -> fp16 O into paQ (reused)
    flash_mma<<<dim3(S_ / 64, B_ * H_), 128, FLASH_SMEM>>>(pQ, pK, pV, paQ);

    // 4) O projection -> fp32 out
    GJobs go;
    go.j[0] = GJob{paQ, pwO, bo, out, nullptr, 0, 1.0f};
    go.j[1] = go.j[0];
    go.j[2] = go.j[0];
    gemm_h<<<dim3(D_ / 128, M_ / 128, 1), 256, GEMM_SMEM>>>(go);
}